// round 2
// baseline (speedup 1.0000x reference)
#include <cuda_runtime.h>
#include <cuda_bf16.h>
#include <math.h>

// Problem constants
#define B_ 32
#define N_ 512
#define D_ 768
#define H_ 12
#define HD_ 64
#define K_ 8
#define BND_ (B_ * N_ * D_)   // 12,582,912
#define KND_ (K_ * N_ * D_)   // 3,145,728
#define ND_  (N_ * D_)        // 393,216

// ---------------- scratch (static device allocations; no cudaMalloc) -------
__device__ float g_S[KND_];
__device__ float g_means[KND_];
__device__ float g_mq[KND_];
__device__ float g_q[BND_];
__device__ float g_k[BND_];
__device__ float g_v[BND_];
__device__ float g_t[BND_];
__device__ float g_vt[BND_];
__device__ float g_ctx[BND_];
__device__ int   g_seg[B_];
__device__ float g_invcnt[K_];

// ---------------- seg + counts (handles int32 or int64 tid) ----------------
__global__ void seg_kernel(const void* __restrict__ tid_raw) {
    __shared__ int s[B_];
    int b = threadIdx.x;
    const int* p32 = (const int*)tid_raw;
    // int64 tid: element 1 (high word of tid[0], values 1..8) is 0.
    // int32 tid: element 1 is a group id in 1..8 (never 0).
    bool is64 = (p32[1] == 0);
    int v;
    if (is64) v = (int)((const long long*)tid_raw)[b];
    else      v = p32[b];
    s[b] = v - 1;
    g_seg[b] = v - 1;
    __syncthreads();
    if (b < K_) {
        int c = 0;
        for (int i = 0; i < B_; i++) c += (s[i] == b) ? 1 : 0;
        g_invcnt[b] = 1.0f / (float)(c > 0 ? c : 1);
    }
}

// ---------------- per-group batch sums: S[g,n,d] ----------------------------
__global__ void group_sum_kernel(const float* __restrict__ hs) {
    __shared__ int seg_s[B_];
    if (threadIdx.x < B_) seg_s[threadIdx.x] = g_seg[threadIdx.x];
    __syncthreads();
    int idx = blockIdx.x * blockDim.x + threadIdx.x;
    if (idx >= ND_) return;
    float acc[K_];
#pragma unroll
    for (int g = 0; g < K_; g++) acc[g] = 0.0f;
#pragma unroll
    for (int b = 0; b < B_; b++) {
        float val = hs[(size_t)b * ND_ + idx];
        int sg = seg_s[b];
#pragma unroll
        for (int g = 0; g < K_; g++) acc[g] += (sg == g) ? val : 0.0f;
    }
#pragma unroll
    for (int g = 0; g < K_; g++) g_S[(size_t)g * ND_ + idx] = acc[g];
}

// ---------------- SGEMM: C[M,768] = A[M,768] @ W[768,768]^T (+epilogue) -----
// EPI 0: C = acc + bias (bias may be null)
// EPI 1: C = (acc + A[row,e]) * invcnt[row>>9] + bias[e]   (means epilogue)
template <int EPI>
__global__ __launch_bounds__(256) void sgemm_kernel(
    const float* __restrict__ A, const float* __restrict__ W,
    const float* __restrict__ bias, float* __restrict__ C)
{
    __shared__ float As[8][128];
    __shared__ float Ws[8][128];
    const int bm = blockIdx.y * 128;
    const int be = blockIdx.x * 128;
    const int t = threadIdx.x;
    const int tx = t & 15, ty = t >> 4;
    const int lrow = t >> 1;
    const int lhalf = (t & 1) * 4;
    const float* Ap = A + (size_t)(bm + lrow) * D_ + lhalf;
    const float* Wp = W + (size_t)(be + lrow) * D_ + lhalf;

    float acc[8][8];
#pragma unroll
    for (int i = 0; i < 8; i++)
#pragma unroll
        for (int j = 0; j < 8; j++) acc[i][j] = 0.0f;

    for (int kt = 0; kt < D_; kt += 8) {
        float4 av = *(const float4*)(Ap + kt);
        float4 wv = *(const float4*)(Wp + kt);
        __syncthreads();
        As[lhalf + 0][lrow] = av.x; As[lhalf + 1][lrow] = av.y;
        As[lhalf + 2][lrow] = av.z; As[lhalf + 3][lrow] = av.w;
        Ws[lhalf + 0][lrow] = wv.x; Ws[lhalf + 1][lrow] = wv.y;
        Ws[lhalf + 2][lrow] = wv.z; Ws[lhalf + 3][lrow] = wv.w;
        __syncthreads();
#pragma unroll
        for (int kk = 0; kk < 8; kk++) {
            float a[8], bb[8];
            *(float4*)&a[0]  = *(const float4*)&As[kk][ty * 8];
            *(float4*)&a[4]  = *(const float4*)&As[kk][ty * 8 + 4];
            *(float4*)&bb[0] = *(const float4*)&Ws[kk][tx * 8];
            *(float4*)&bb[4] = *(const float4*)&Ws[kk][tx * 8 + 4];
#pragma unroll
            for (int i = 0; i < 8; i++)
#pragma unroll
                for (int j = 0; j < 8; j++) acc[i][j] += a[i] * bb[j];
        }
    }

#pragma unroll
    for (int i = 0; i < 8; i++) {
        int row = bm + ty * 8 + i;
        float sc = (EPI == 1) ? g_invcnt[row >> 9] : 1.0f;
#pragma unroll
        for (int j = 0; j < 8; j++) {
            int e = be + tx * 8 + j;
            float v = acc[i][j];
            if (EPI == 1) v = (v + A[(size_t)row * D_ + e]) * sc;
            if (bias) v += bias[e];
            C[(size_t)row * D_ + e] = v;
        }
    }
}

// ---------------- t = q + mq[seg] -------------------------------------------
__global__ void add_t_kernel(void) {
    int idx4 = blockIdx.x * blockDim.x + threadIdx.x;
    if (idx4 >= BND_ / 4) return;
    int idx = idx4 * 4;
    int b = idx / ND_;
    int off = idx - b * ND_;
    int sg = g_seg[b];
    float4 qv = *(const float4*)&g_q[idx];
    float4 mv = *(const float4*)&g_mq[(size_t)sg * ND_ + off];
    float4 r;
    r.x = qv.x + mv.x; r.y = qv.y + mv.y;
    r.z = qv.z + mv.z; r.w = qv.w + mv.w;
    *(float4*)&g_t[idx] = r;
}

// ---------------- flash attention (fp32, BM=64, BN=32) ----------------------
// Layout: [B, N, D] with head h occupying cols h*64..h*64+63. Softmax over N keys.
__global__ __launch_bounds__(256) void attn_kernel(
    const float* __restrict__ Qg, const float* __restrict__ Kg,
    const float* __restrict__ Vg, float* __restrict__ Og)
{
    __shared__ float Qs[64][68];   // [row][d], scaled by 1/8
    __shared__ float Ks[64][33];   // [d][c]
    __shared__ float Vs[32][68];   // [c][d]
    __shared__ float Ps[64][33];   // [row][c]

    const int b = blockIdx.z, h = blockIdx.y;
    const int n0 = blockIdx.x * 64;
    const size_t base = (size_t)b * ND_ + (size_t)h * HD_;
    const float* Qb = Qg + base + (size_t)n0 * D_;
    const float* Kb = Kg + base;
    const float* Vb = Vg + base;
    float*       Ob = Og + base + (size_t)n0 * D_;

    const int t = threadIdx.x;
    const int tx = t & 15, ty = t >> 4;

    // load Q tile (64x64), fold in softmax scale 1/sqrt(64)=0.125
    {
        int row = t >> 2;
        int c0 = (t & 3) * 16;
        const float* src = Qb + (size_t)row * D_ + c0;
#pragma unroll
        for (int i = 0; i < 16; i += 4) {
            float4 v = *(const float4*)(src + i);
            Qs[row][c0 + i + 0] = v.x * 0.125f;
            Qs[row][c0 + i + 1] = v.y * 0.125f;
            Qs[row][c0 + i + 2] = v.z * 0.125f;
            Qs[row][c0 + i + 3] = v.w * 0.125f;
        }
    }

    float o[4][4];
#pragma unroll
    for (int i = 0; i < 4; i++)
#pragma unroll
        for (int j = 0; j < 4; j++) o[i][j] = 0.0f;
    float m[4] = {-INFINITY, -INFINITY, -INFINITY, -INFINITY};
    float l[4] = {0.0f, 0.0f, 0.0f, 0.0f};

    for (int kt = 0; kt < N_; kt += 32) {
        __syncthreads();   // previous tile consumed (also orders Q load on iter 0)
        // load K tile -> Ks[d][c], V tile -> Vs[c][d]
        {
            int c = t >> 3;
            int d0 = (t & 7) * 8;
            const float* ksrc = Kb + (size_t)(kt + c) * D_ + d0;
            const float* vsrc = Vb + (size_t)(kt + c) * D_ + d0;
            float4 k0 = *(const float4*)(ksrc);
            float4 k1 = *(const float4*)(ksrc + 4);
            float4 v0 = *(const float4*)(vsrc);
            float4 v1 = *(const float4*)(vsrc + 4);
            Ks[d0 + 0][c] = k0.x; Ks[d0 + 1][c] = k0.y;
            Ks[d0 + 2][c] = k0.z; Ks[d0 + 3][c] = k0.w;
            Ks[d0 + 4][c] = k1.x; Ks[d0 + 5][c] = k1.y;
            Ks[d0 + 6][c] = k1.z; Ks[d0 + 7][c] = k1.w;
            *(float4*)&Vs[c][d0]     = v0;
            *(float4*)&Vs[c][d0 + 4] = v1;
        }
        __syncthreads();

        // S = Q K^T : rows 4*ty+i, cols 2*tx+j
        float s[4][2];
#pragma unroll
        for (int i = 0; i < 4; i++) { s[i][0] = 0.0f; s[i][1] = 0.0f; }
#pragma unroll 16
        for (int d = 0; d < 64; d++) {
            float b0 = Ks[d][2 * tx + 0];
            float b1 = Ks[d][2 * tx + 1];
#pragma unroll
            for (int i = 0; i < 4; i++) {
                float a = Qs[4 * ty + i][d];
                s[i][0] += a * b0;
                s[i][1] += a * b1;
            }
        }

        // online softmax: row max over the 32-col tile (reduce over tx lanes)
        float mt[4];
#pragma unroll
        for (int i = 0; i < 4; i++) mt[i] = fmaxf(s[i][0], s[i][1]);
#pragma unroll
        for (int off = 1; off < 16; off <<= 1)
#pragma unroll
            for (int i = 0; i < 4; i++)
                mt[i] = fmaxf(mt[i], __shfl_xor_sync(0xffffffffu, mt[i], off));

        float corr[4];
#pragma unroll
        for (int i = 0; i < 4; i++) {
            float mn = fmaxf(m[i], mt[i]);
            corr[i] = __expf(m[i] - mn);
            m[i] = mn;
        }
        float ls[4];
#pragma unroll
        for (int i = 0; i < 4; i++) {
            float p0 = __expf(s[i][0] - m[i]);
            float p1 = __expf(s[i][1] - m[i]);
            Ps[4 * ty + i][2 * tx + 0] = p0;
            Ps[4 * ty + i][2 * tx + 1] = p1;
            ls[i] = p0 + p1;
        }
#pragma unroll
        for (int off = 1; off < 16; off <<= 1)
#pragma unroll
            for (int i = 0; i < 4; i++)
                ls[i] += __shfl_xor_sync(0xffffffffu, ls[i], off);
#pragma unroll
        for (int i = 0; i < 4; i++) l[i] = l[i] * corr[i] + ls[i];
#pragma unroll
        for (int i = 0; i < 4; i++)
#pragma unroll
            for (int j = 0; j < 4; j++) o[i][j] *= corr[i];
        __syncthreads();   // Ps visible

        // O += P V : cols 4*tx+j
#pragma unroll 8
        for (int kk = 0; kk < 32; kk++) {
            float4 bv = *(const float4*)&Vs[kk][4 * tx];
#pragma unroll
            for (int i = 0; i < 4; i++) {
                float a = Ps[4 * ty + i][kk];
                o[i][0] += a * bv.x;
                o[i][1] += a * bv.y;
                o[i][2] += a * bv.z;
                o[i][3] += a * bv.w;
            }
        }
    }

#pragma unroll
    for (int i = 0; i < 4; i++) {
        float inv = 1.0f / l[i];
        float4 r;
        r.x = o[i][0] * inv; r.y = o[i][1] * inv;
        r.z = o[i][2] * inv; r.w = o[i][3] * inv;
        *(float4*)&Ob[(size_t)(4 * ty + i) * D_ + 4 * tx] = r;
    }
}

// ---------------- host ------------------------------------------------------
extern "C" void kernel_launch(void* const* d_in, const int* in_sizes, int n_in,
                              void* d_out, int out_size)
{
    const float* hs  = (const float*)d_in[0];
    const void*  tid = d_in[1];
    const float* Wq = (const float*)d_in[2];
    const float* bq = (const float*)d_in[3];
    const float* Wk = (const float*)d_in[4];
    const float* bk = (const float*)d_in[5];
    const float* Wv = (const float*)d_in[6];
    const float* bv = (const float*)d_in[7];
    const float* Wo = (const float*)d_in[8];
    const float* bo = (const float*)d_in[9];
    const float* Wc = (const float*)d_in[10];
    const float* bc = (const float*)d_in[11];
    float* out = (float*)d_out;

    float *pS, *pMeans, *pMq, *pQ, *pK, *pV, *pT, *pVt, *pCtx;
    cudaGetSymbolAddress((void**)&pS, g_S);
    cudaGetSymbolAddress((void**)&pMeans, g_means);
    cudaGetSymbolAddress((void**)&pMq, g_mq);
    cudaGetSymbolAddress((void**)&pQ, g_q);
    cudaGetSymbolAddress((void**)&pK, g_k);
    cudaGetSymbolAddress((void**)&pV, g_v);
    cudaGetSymbolAddress((void**)&pT, g_t);
    cudaGetSymbolAddress((void**)&pVt, g_vt);
    cudaGetSymbolAddress((void**)&pCtx, g_ctx);

    // 1) segment ids + inverse counts
    seg_kernel<<<1, B_>>>(tid);
    // 2) per-group batch sums S[K,N,D]
    group_sum_kernel<<<ND_ / 256, 256>>>(hs);
    // 3) means = (S + S@Wc^T) * invcnt + bc   [K*N = 4096 rows]
    {
        dim3 g(D_ / 128, (K_ * N_) / 128);
        sgemm_kernel<1><<<g, 256>>>(pS, Wc, bc, pMeans);
    }
    // 4) q,k,v projections of hs   [B*N = 16384 rows]
    {
        dim3 g(D_ / 128, (B_ * N_) / 128);
        sgemm_kernel<0><<<g, 256>>>(hs, Wq, bq, pQ);
        sgemm_kernel<0><<<g, 256>>>(hs, Wk, bk, pK);
        sgemm_kernel<0><<<g, 256>>>(hs, Wv, bv, pV);
    }
    // 5) mq = means @ Wq^T (no bias; bias already in q)
    {
        dim3 g(D_ / 128, (K_ * N_) / 128);
        sgemm_kernel<0><<<g, 256>>>(pMeans, Wq, nullptr, pMq);
    }
    // 6) t = q + mq[seg]
    add_t_kernel<<<(BND_ / 4) / 256, 256>>>();
    // 7) stage 1: v_t = softmax(t k^T / 8) v
    {
        dim3 g(N_ / 64, H_, B_);
        attn_kernel<<<g, 256>>>(pT, pK, pV, pVt);
        // 8) stage 2: ctx = softmax(q t^T / 8) v_t
        attn_kernel<<<g, 256>>>(pQ, pT, pVt, pCtx);
    }
    // 9) out = ctx @ Wo^T + bo
    {
        dim3 g(D_ / 128, (B_ * N_) / 128);
        sgemm_kernel<0><<<g, 256>>>(pCtx, Wo, bo, out);
    }
}

// round 3
// speedup vs baseline: 2.2372x; 2.2372x over previous
#include <cuda_runtime.h>
#include <cuda_bf16.h>
#include <math.h>
#include <stdint.h>

// Problem constants
#define B_ 32
#define N_ 512
#define D_ 768
#define H_ 12
#define HD_ 64
#define K_ 8
#define BND_ (B_ * N_ * D_)   // 12,582,912
#define KND_ (K_ * N_ * D_)   // 3,145,728
#define ND_  (N_ * D_)        // 393,216

// ---------------- scratch (static device allocations; no cudaMalloc) -------
__device__ float g_S[KND_];
__device__ float g_means[KND_];
__device__ float g_mq[KND_];
__device__ float g_q[BND_];
__device__ float g_k[BND_];
__device__ float g_v[BND_];
__device__ float g_t[BND_];
__device__ float g_vt[BND_];
__device__ float g_ctx[BND_];
__device__ int   g_seg[B_];
__device__ float g_invcnt[K_];

// ---------------- seg + counts (handles int32 or int64 tid) ----------------
__global__ void seg_kernel(const void* __restrict__ tid_raw) {
    __shared__ int s[B_];
    int b = threadIdx.x;
    const int* p32 = (const int*)tid_raw;
    bool is64 = (p32[1] == 0);
    int v;
    if (is64) v = (int)((const long long*)tid_raw)[b];
    else      v = p32[b];
    s[b] = v - 1;
    g_seg[b] = v - 1;
    __syncthreads();
    if (b < K_) {
        int c = 0;
        for (int i = 0; i < B_; i++) c += (s[i] == b) ? 1 : 0;
        g_invcnt[b] = 1.0f / (float)(c > 0 ? c : 1);
    }
}

// ---------------- per-group batch sums: S[g,n,d] ----------------------------
__global__ void group_sum_kernel(const float* __restrict__ hs) {
    __shared__ int seg_s[B_];
    if (threadIdx.x < B_) seg_s[threadIdx.x] = g_seg[threadIdx.x];
    __syncthreads();
    int idx = blockIdx.x * blockDim.x + threadIdx.x;
    if (idx >= ND_) return;
    float acc[K_];
#pragma unroll
    for (int g = 0; g < K_; g++) acc[g] = 0.0f;
#pragma unroll
    for (int b = 0; b < B_; b++) {
        float val = hs[(size_t)b * ND_ + idx];
        int sg = seg_s[b];
#pragma unroll
        for (int g = 0; g < K_; g++) acc[g] += (sg == g) ? val : 0.0f;
    }
#pragma unroll
    for (int g = 0; g < K_; g++) g_S[(size_t)g * ND_ + idx] = acc[g];
}

// ---------------- tf32 helpers ----------------------------------------------
__device__ __forceinline__ uint32_t f2tf32(float x) {
    uint32_t r;
    asm("cvt.rna.tf32.f32 %0, %1;" : "=r"(r) : "f"(x));
    return r;
}

__device__ __forceinline__ void mma_tf32(
    float& c0, float& c1, float& c2, float& c3,
    uint32_t a0, uint32_t a1, uint32_t a2, uint32_t a3,
    uint32_t b0, uint32_t b1)
{
    asm volatile(
        "mma.sync.aligned.m16n8k8.row.col.f32.tf32.tf32.f32 "
        "{%0,%1,%2,%3},{%4,%5,%6,%7},{%8,%9},{%0,%1,%2,%3};"
        : "+f"(c0), "+f"(c1), "+f"(c2), "+f"(c3)
        : "r"(a0), "r"(a1), "r"(a2), "r"(a3), "r"(b0), "r"(b1));
}

// ---------------- TF32 GEMM: C[M,768] = A[M,768] @ W[768,768]^T (+epilogue) -
// EPI 0: C = acc + bias (bias may be null)
// EPI 1: C = (acc + A[row,e]) * invcnt[row>>9] + bias[e]   (means epilogue)
// Block 128x128, BK=16, 8 warps (2x4: warp tile 64x32 = 4x4 m16n8k8).
// Smem layout transposed [k][m] / [k][n] with word stride 136 (conflict-free
// fragment reads: tlane stride 136 -> bank stride 8).
#define KSTR 136
template <int EPI>
__global__ __launch_bounds__(256, 2) void tf32_gemm_kernel(
    const float* __restrict__ A, const float* __restrict__ W,
    const float* __restrict__ bias, float* __restrict__ C)
{
    __shared__ uint32_t As[16 * KSTR];
    __shared__ uint32_t Ws[16 * KSTR];

    const int bm = blockIdx.y * 128;
    const int bn = blockIdx.x * 128;
    const int t = threadIdx.x;
    const int lane = t & 31;
    const int warp = t >> 5;
    const int wm = (warp & 1) * 64;   // warp m-offset within block
    const int wn = (warp >> 1) * 32;  // warp n-offset within block
    const int groupID = lane >> 2;
    const int tlane = lane & 3;

    // gmem tile-load mapping: thread -> (m = t&127, k-half = t>>7)
    const int lm = t & 127;
    const int lk = (t >> 7) * 8;
    const float* Ap = A + (size_t)(bm + lm) * D_ + lk;
    const float* Wp = W + (size_t)(bn + lm) * D_ + lk;

    float c[4][4][4];
#pragma unroll
    for (int i = 0; i < 4; i++)
#pragma unroll
        for (int j = 0; j < 4; j++)
#pragma unroll
            for (int r = 0; r < 4; r++) c[i][j][r] = 0.0f;

    // prologue: load tile kt=0 into smem
    {
        float4 ax = *(const float4*)(Ap);
        float4 ay = *(const float4*)(Ap + 4);
        float4 wx = *(const float4*)(Wp);
        float4 wy = *(const float4*)(Wp + 4);
        As[(lk + 0) * KSTR + lm] = f2tf32(ax.x);
        As[(lk + 1) * KSTR + lm] = f2tf32(ax.y);
        As[(lk + 2) * KSTR + lm] = f2tf32(ax.z);
        As[(lk + 3) * KSTR + lm] = f2tf32(ax.w);
        As[(lk + 4) * KSTR + lm] = f2tf32(ay.x);
        As[(lk + 5) * KSTR + lm] = f2tf32(ay.y);
        As[(lk + 6) * KSTR + lm] = f2tf32(ay.z);
        As[(lk + 7) * KSTR + lm] = f2tf32(ay.w);
        Ws[(lk + 0) * KSTR + lm] = f2tf32(wx.x);
        Ws[(lk + 1) * KSTR + lm] = f2tf32(wx.y);
        Ws[(lk + 2) * KSTR + lm] = f2tf32(wx.z);
        Ws[(lk + 3) * KSTR + lm] = f2tf32(wx.w);
        Ws[(lk + 4) * KSTR + lm] = f2tf32(wy.x);
        Ws[(lk + 5) * KSTR + lm] = f2tf32(wy.y);
        Ws[(lk + 6) * KSTR + lm] = f2tf32(wy.z);
        Ws[(lk + 7) * KSTR + lm] = f2tf32(wy.w);
    }
    __syncthreads();

    for (int kt = 16; kt <= D_; kt += 16) {
        // prefetch next tile into registers while computing current
        float4 ax, ay, wx, wy;
        const bool more = (kt < D_);
        if (more) {
            ax = *(const float4*)(Ap + kt);
            ay = *(const float4*)(Ap + kt + 4);
            wx = *(const float4*)(Wp + kt);
            wy = *(const float4*)(Wp + kt + 4);
        }

        // compute current smem tile: 2 k-steps of 8
#pragma unroll
        for (int ks = 0; ks < 16; ks += 8) {
            uint32_t af[4][4];
            uint32_t bf[4][2];
            const int kb = (ks + tlane) * KSTR;
#pragma unroll
            for (int mt = 0; mt < 4; mt++) {
                int m0 = wm + mt * 16 + groupID;
                af[mt][0] = As[kb + m0];
                af[mt][1] = As[kb + m0 + 8];
                af[mt][2] = As[kb + 4 * KSTR + m0];
                af[mt][3] = As[kb + 4 * KSTR + m0 + 8];
            }
#pragma unroll
            for (int nt = 0; nt < 4; nt++) {
                int n0 = wn + nt * 8 + groupID;
                bf[nt][0] = Ws[kb + n0];
                bf[nt][1] = Ws[kb + 4 * KSTR + n0];
            }
#pragma unroll
            for (int mt = 0; mt < 4; mt++)
#pragma unroll
                for (int nt = 0; nt < 4; nt++)
                    mma_tf32(c[mt][nt][0], c[mt][nt][1], c[mt][nt][2], c[mt][nt][3],
                             af[mt][0], af[mt][1], af[mt][2], af[mt][3],
                             bf[nt][0], bf[nt][1]);
        }

        if (more) {
            __syncthreads();
            As[(lk + 0) * KSTR + lm] = f2tf32(ax.x);
            As[(lk + 1) * KSTR + lm] = f2tf32(ax.y);
            As[(lk + 2) * KSTR + lm] = f2tf32(ax.z);
            As[(lk + 3) * KSTR + lm] = f2tf32(ax.w);
            As[(lk + 4) * KSTR + lm] = f2tf32(ay.x);
            As[(lk + 5) * KSTR + lm] = f2tf32(ay.y);
            As[(lk + 6) * KSTR + lm] = f2tf32(ay.z);
            As[(lk + 7) * KSTR + lm] = f2tf32(ay.w);
            Ws[(lk + 0) * KSTR + lm] = f2tf32(wx.x);
            Ws[(lk + 1) * KSTR + lm] = f2tf32(wx.y);
            Ws[(lk + 2) * KSTR + lm] = f2tf32(wx.z);
            Ws[(lk + 3) * KSTR + lm] = f2tf32(wx.w);
            Ws[(lk + 4) * KSTR + lm] = f2tf32(wy.x);
            Ws[(lk + 5) * KSTR + lm] = f2tf32(wy.y);
            Ws[(lk + 6) * KSTR + lm] = f2tf32(wy.z);
            Ws[(lk + 7) * KSTR + lm] = f2tf32(wy.w);
            __syncthreads();
        }
    }

    // epilogue
#pragma unroll
    for (int mt = 0; mt < 4; mt++) {
#pragma unroll
        for (int rr = 0; rr < 2; rr++) {
            int row = bm + wm + mt * 16 + groupID + rr * 8;
            float sc = (EPI == 1) ? g_invcnt[row >> 9] : 1.0f;
#pragma unroll
            for (int nt = 0; nt < 4; nt++) {
                int col = bn + wn + nt * 8 + tlane * 2;
                float v0 = c[mt][nt][rr * 2 + 0];
                float v1 = c[mt][nt][rr * 2 + 1];
                if (EPI == 1) {
                    v0 = (v0 + A[(size_t)row * D_ + col]) * sc;
                    v1 = (v1 + A[(size_t)row * D_ + col + 1]) * sc;
                }
                if (bias) {
                    v0 += bias[col];
                    v1 += bias[col + 1];
                }
                float2 r2;
                r2.x = v0; r2.y = v1;
                *(float2*)&C[(size_t)row * D_ + col] = r2;
            }
        }
    }
}

// ---------------- t = q + mq[seg] -------------------------------------------
__global__ void add_t_kernel(void) {
    int idx4 = blockIdx.x * blockDim.x + threadIdx.x;
    if (idx4 >= BND_ / 4) return;
    int idx = idx4 * 4;
    int b = idx / ND_;
    int off = idx - b * ND_;
    int sg = g_seg[b];
    float4 qv = *(const float4*)&g_q[idx];
    float4 mv = *(const float4*)&g_mq[(size_t)sg * ND_ + off];
    float4 r;
    r.x = qv.x + mv.x; r.y = qv.y + mv.y;
    r.z = qv.z + mv.z; r.w = qv.w + mv.w;
    *(float4*)&g_t[idx] = r;
}

// ---------------- flash attention (fp32, BM=64, BN=32) ----------------------
__global__ __launch_bounds__(256) void attn_kernel(
    const float* __restrict__ Qg, const float* __restrict__ Kg,
    const float* __restrict__ Vg, float* __restrict__ Og)
{
    __shared__ float Qs[64][68];   // [row][d], scaled by 1/8
    __shared__ float Ks[64][33];   // [d][c]
    __shared__ float Vs[32][68];   // [c][d]
    __shared__ float Ps[64][33];   // [row][c]

    const int b = blockIdx.z, h = blockIdx.y;
    const int n0 = blockIdx.x * 64;
    const size_t base = (size_t)b * ND_ + (size_t)h * HD_;
    const float* Qb = Qg + base + (size_t)n0 * D_;
    const float* Kb = Kg + base;
    const float* Vb = Vg + base;
    float*       Ob = Og + base + (size_t)n0 * D_;

    const int t = threadIdx.x;
    const int tx = t & 15, ty = t >> 4;

    {
        int row = t >> 2;
        int c0 = (t & 3) * 16;
        const float* src = Qb + (size_t)row * D_ + c0;
#pragma unroll
        for (int i = 0; i < 16; i += 4) {
            float4 v = *(const float4*)(src + i);
            Qs[row][c0 + i + 0] = v.x * 0.125f;
            Qs[row][c0 + i + 1] = v.y * 0.125f;
            Qs[row][c0 + i + 2] = v.z * 0.125f;
            Qs[row][c0 + i + 3] = v.w * 0.125f;
        }
    }

    float o[4][4];
#pragma unroll
    for (int i = 0; i < 4; i++)
#pragma unroll
        for (int j = 0; j < 4; j++) o[i][j] = 0.0f;
    float m[4] = {-INFINITY, -INFINITY, -INFINITY, -INFINITY};
    float l[4] = {0.0f, 0.0f, 0.0f, 0.0f};

    for (int kt = 0; kt < N_; kt += 32) {
        __syncthreads();
        {
            int c = t >> 3;
            int d0 = (t & 7) * 8;
            const float* ksrc = Kb + (size_t)(kt + c) * D_ + d0;
            const float* vsrc = Vb + (size_t)(kt + c) * D_ + d0;
            float4 k0 = *(const float4*)(ksrc);
            float4 k1 = *(const float4*)(ksrc + 4);
            float4 v0 = *(const float4*)(vsrc);
            float4 v1 = *(const float4*)(vsrc + 4);
            Ks[d0 + 0][c] = k0.x; Ks[d0 + 1][c] = k0.y;
            Ks[d0 + 2][c] = k0.z; Ks[d0 + 3][c] = k0.w;
            Ks[d0 + 4][c] = k1.x; Ks[d0 + 5][c] = k1.y;
            Ks[d0 + 6][c] = k1.z; Ks[d0 + 7][c] = k1.w;
            *(float4*)&Vs[c][d0]     = v0;
            *(float4*)&Vs[c][d0 + 4] = v1;
        }
        __syncthreads();

        float s[4][2];
#pragma unroll
        for (int i = 0; i < 4; i++) { s[i][0] = 0.0f; s[i][1] = 0.0f; }
#pragma unroll 16
        for (int d = 0; d < 64; d++) {
            float b0 = Ks[d][2 * tx + 0];
            float b1 = Ks[d][2 * tx + 1];
#pragma unroll
            for (int i = 0; i < 4; i++) {
                float a = Qs[4 * ty + i][d];
                s[i][0] += a * b0;
                s[i][1] += a * b1;
            }
        }

        float mt[4];
#pragma unroll
        for (int i = 0; i < 4; i++) mt[i] = fmaxf(s[i][0], s[i][1]);
#pragma unroll
        for (int off = 1; off < 16; off <<= 1)
#pragma unroll
            for (int i = 0; i < 4; i++)
                mt[i] = fmaxf(mt[i], __shfl_xor_sync(0xffffffffu, mt[i], off));

        float corr[4];
#pragma unroll
        for (int i = 0; i < 4; i++) {
            float mn = fmaxf(m[i], mt[i]);
            corr[i] = __expf(m[i] - mn);
            m[i] = mn;
        }
        float ls[4];
#pragma unroll
        for (int i = 0; i < 4; i++) {
            float p0 = __expf(s[i][0] - m[i]);
            float p1 = __expf(s[i][1] - m[i]);
            Ps[4 * ty + i][2 * tx + 0] = p0;
            Ps[4 * ty + i][2 * tx + 1] = p1;
            ls[i] = p0 + p1;
        }
#pragma unroll
        for (int off = 1; off < 16; off <<= 1)
#pragma unroll
            for (int i = 0; i < 4; i++)
                ls[i] += __shfl_xor_sync(0xffffffffu, ls[i], off);
#pragma unroll
        for (int i = 0; i < 4; i++) l[i] = l[i] * corr[i] + ls[i];
#pragma unroll
        for (int i = 0; i < 4; i++)
#pragma unroll
            for (int j = 0; j < 4; j++) o[i][j] *= corr[i];
        __syncthreads();

#pragma unroll 8
        for (int kk = 0; kk < 32; kk++) {
            float4 bv = *(const float4*)&Vs[kk][4 * tx];
#pragma unroll
            for (int i = 0; i < 4; i++) {
                float a = Ps[4 * ty + i][kk];
                o[i][0] += a * bv.x;
                o[i][1] += a * bv.y;
                o[i][2] += a * bv.z;
                o[i][3] += a * bv.w;
            }
        }
    }

#pragma unroll
    for (int i = 0; i < 4; i++) {
        float inv = 1.0f / l[i];
        float4 r;
        r.x = o[i][0] * inv; r.y = o[i][1] * inv;
        r.z = o[i][2] * inv; r.w = o[i][3] * inv;
        *(float4*)&Ob[(size_t)(4 * ty + i) * D_ + 4 * tx] = r;
    }
}

// ---------------- host ------------------------------------------------------
extern "C" void kernel_launch(void* const* d_in, const int* in_sizes, int n_in,
                              void* d_out, int out_size)
{
    const float* hs  = (const float*)d_in[0];
    const void*  tid = d_in[1];
    const float* Wq = (const float*)d_in[2];
    const float* bq = (const float*)d_in[3];
    const float* Wk = (const float*)d_in[4];
    const float* bk = (const float*)d_in[5];
    const float* Wv = (const float*)d_in[6];
    const float* bv = (const float*)d_in[7];
    const float* Wo = (const float*)d_in[8];
    const float* bo = (const float*)d_in[9];
    const float* Wc = (const float*)d_in[10];
    const float* bc = (const float*)d_in[11];
    float* out = (float*)d_out;

    float *pS, *pMeans, *pMq, *pQ, *pK, *pV, *pT, *pVt, *pCtx;
    cudaGetSymbolAddress((void**)&pS, g_S);
    cudaGetSymbolAddress((void**)&pMeans, g_means);
    cudaGetSymbolAddress((void**)&pMq, g_mq);
    cudaGetSymbolAddress((void**)&pQ, g_q);
    cudaGetSymbolAddress((void**)&pK, g_k);
    cudaGetSymbolAddress((void**)&pV, g_v);
    cudaGetSymbolAddress((void**)&pT, g_t);
    cudaGetSymbolAddress((void**)&pVt, g_vt);
    cudaGetSymbolAddress((void**)&pCtx, g_ctx);

    // 1) segment ids + inverse counts
    seg_kernel<<<1, B_>>>(tid);
    // 2) per-group batch sums S[K,N,D]
    group_sum_kernel<<<ND_ / 256, 256>>>(hs);
    // 3) means = (S + S@Wc^T) * invcnt + bc   [K*N = 4096 rows]
    {
        dim3 g(D_ / 128, (K_ * N_) / 128);
        tf32_gemm_kernel<1><<<g, 256>>>(pS, Wc, bc, pMeans);
    }
    // 4) q,k,v projections of hs   [B*N = 16384 rows]
    {
        dim3 g(D_ / 128, (B_ * N_) / 128);
        tf32_gemm_kernel<0><<<g, 256>>>(hs, Wq, bq, pQ);
        tf32_gemm_kernel<0><<<g, 256>>>(hs, Wk, bk, pK);
        tf32_gemm_kernel<0><<<g, 256>>>(hs, Wv, bv, pV);
    }
    // 5) mq = means @ Wq^T (no bias; bias already in q)
    {
        dim3 g(D_ / 128, (K_ * N_) / 128);
        tf32_gemm_kernel<0><<<g, 256>>>(pMeans, Wq, nullptr, pMq);
    }
    // 6) t = q + mq[seg]
    add_t_kernel<<<(BND_ / 4) / 256, 256>>>();
    // 7) stage 1: v_t = softmax(t k^T / 8) v
    {
        dim3 g(N_ / 64, H_, B_);
        attn_kernel<<<g, 256>>>(pT, pK, pV, pVt);
        // 8) stage 2: ctx = softmax(q t^T / 8) v_t
        attn_kernel<<<g, 256>>>(pQ, pT, pVt, pCtx);
    }
    // 9) out = ctx @ Wo^T + bo
    {
        dim3 g(D_ / 128, (B_ * N_) / 128);
        tf32_gemm_kernel<0><<<g, 256>>>(pCtx, Wo, bo, out);
    }
}

// round 5
// speedup vs baseline: 2.7956x; 1.2496x over previous
#include <cuda_runtime.h>
#include <cuda_bf16.h>
#include <math.h>
#include <stdint.h>

// Problem constants
#define B_ 32
#define N_ 512
#define D_ 768
#define H_ 12
#define HD_ 64
#define K_ 8
#define BND_ (B_ * N_ * D_)   // 12,582,912
#define KND_ (K_ * N_ * D_)   // 3,145,728
#define ND_  (N_ * D_)        // 393,216

// ---------------- scratch (static device allocations; no cudaMalloc) -------
__device__ float g_S[KND_];
__device__ float g_means[KND_];
__device__ float g_mq[KND_];
__device__ float g_q[BND_];
__device__ float g_k[BND_];
__device__ float g_v[BND_];
__device__ float g_t[BND_];
__device__ float g_vt[BND_];
__device__ float g_ctx[BND_];
__device__ int   g_seg[B_];
__device__ float g_invcnt[K_];

// ---------------- seg + counts (handles int32 or int64 tid) ----------------
__global__ void seg_kernel(const void* __restrict__ tid_raw) {
    __shared__ int s[B_];
    int b = threadIdx.x;
    const int* p32 = (const int*)tid_raw;
    bool is64 = (p32[1] == 0);
    int v;
    if (is64) v = (int)((const long long*)tid_raw)[b];
    else      v = p32[b];
    s[b] = v - 1;
    g_seg[b] = v - 1;
    __syncthreads();
    if (b < K_) {
        int c = 0;
        for (int i = 0; i < B_; i++) c += (s[i] == b) ? 1 : 0;
        g_invcnt[b] = 1.0f / (float)(c > 0 ? c : 1);
    }
}

// ---------------- per-group batch sums: S[g,n,d] ----------------------------
__global__ void group_sum_kernel(const float* __restrict__ hs) {
    __shared__ int seg_s[B_];
    if (threadIdx.x < B_) seg_s[threadIdx.x] = g_seg[threadIdx.x];
    __syncthreads();
    int idx = blockIdx.x * blockDim.x + threadIdx.x;
    if (idx >= ND_) return;
    float acc[K_];
#pragma unroll
    for (int g = 0; g < K_; g++) acc[g] = 0.0f;
#pragma unroll
    for (int b = 0; b < B_; b++) {
        float val = hs[(size_t)b * ND_ + idx];
        int sg = seg_s[b];
#pragma unroll
        for (int g = 0; g < K_; g++) acc[g] += (sg == g) ? val : 0.0f;
    }
#pragma unroll
    for (int g = 0; g < K_; g++) g_S[(size_t)g * ND_ + idx] = acc[g];
}

// ---------------- tf32 helpers ----------------------------------------------
__device__ __forceinline__ uint32_t f2tf32(float x) {
    uint32_t r;
    asm("cvt.rna.tf32.f32 %0, %1;" : "=r"(r) : "f"(x));
    return r;
}

__device__ __forceinline__ void mma_tf32(
    float& c0, float& c1, float& c2, float& c3,
    uint32_t a0, uint32_t a1, uint32_t a2, uint32_t a3,
    uint32_t b0, uint32_t b1)
{
    asm volatile(
        "mma.sync.aligned.m16n8k8.row.col.f32.tf32.tf32.f32 "
        "{%0,%1,%2,%3},{%4,%5,%6,%7},{%8,%9},{%0,%1,%2,%3};"
        : "+f"(c0), "+f"(c1), "+f"(c2), "+f"(c3)
        : "r"(a0), "r"(a1), "r"(a2), "r"(a3), "r"(b0), "r"(b1));
}

// ---------------- TF32 GEMM: C[M,768] = A[M,768] @ W[768,768]^T (+epilogue) -
#define KSTR 136
template <int EPI>
__global__ __launch_bounds__(256, 2) void tf32_gemm_kernel(
    const float* __restrict__ A, const float* __restrict__ W,
    const float* __restrict__ bias, float* __restrict__ C)
{
    __shared__ uint32_t As[16 * KSTR];
    __shared__ uint32_t Ws[16 * KSTR];

    const int bm = blockIdx.y * 128;
    const int bn = blockIdx.x * 128;
    const int t = threadIdx.x;
    const int lane = t & 31;
    const int warp = t >> 5;
    const int wm = (warp & 1) * 64;
    const int wn = (warp >> 1) * 32;
    const int groupID = lane >> 2;
    const int tlane = lane & 3;

    const int lm = t & 127;
    const int lk = (t >> 7) * 8;
    const float* Ap = A + (size_t)(bm + lm) * D_ + lk;
    const float* Wp = W + (size_t)(bn + lm) * D_ + lk;

    float c[4][4][4];
#pragma unroll
    for (int i = 0; i < 4; i++)
#pragma unroll
        for (int j = 0; j < 4; j++)
#pragma unroll
            for (int r = 0; r < 4; r++) c[i][j][r] = 0.0f;

    {
        float4 ax = *(const float4*)(Ap);
        float4 ay = *(const float4*)(Ap + 4);
        float4 wx = *(const float4*)(Wp);
        float4 wy = *(const float4*)(Wp + 4);
        As[(lk + 0) * KSTR + lm] = f2tf32(ax.x);
        As[(lk + 1) * KSTR + lm] = f2tf32(ax.y);
        As[(lk + 2) * KSTR + lm] = f2tf32(ax.z);
        As[(lk + 3) * KSTR + lm] = f2tf32(ax.w);
        As[(lk + 4) * KSTR + lm] = f2tf32(ay.x);
        As[(lk + 5) * KSTR + lm] = f2tf32(ay.y);
        As[(lk + 6) * KSTR + lm] = f2tf32(ay.z);
        As[(lk + 7) * KSTR + lm] = f2tf32(ay.w);
        Ws[(lk + 0) * KSTR + lm] = f2tf32(wx.x);
        Ws[(lk + 1) * KSTR + lm] = f2tf32(wx.y);
        Ws[(lk + 2) * KSTR + lm] = f2tf32(wx.z);
        Ws[(lk + 3) * KSTR + lm] = f2tf32(wx.w);
        Ws[(lk + 4) * KSTR + lm] = f2tf32(wy.x);
        Ws[(lk + 5) * KSTR + lm] = f2tf32(wy.y);
        Ws[(lk + 6) * KSTR + lm] = f2tf32(wy.z);
        Ws[(lk + 7) * KSTR + lm] = f2tf32(wy.w);
    }
    __syncthreads();

    for (int kt = 16; kt <= D_; kt += 16) {
        float4 ax, ay, wx, wy;
        const bool more = (kt < D_);
        if (more) {
            ax = *(const float4*)(Ap + kt);
            ay = *(const float4*)(Ap + kt + 4);
            wx = *(const float4*)(Wp + kt);
            wy = *(const float4*)(Wp + kt + 4);
        }

#pragma unroll
        for (int ks = 0; ks < 16; ks += 8) {
            uint32_t af[4][4];
            uint32_t bf[4][2];
            const int kb = (ks + tlane) * KSTR;
#pragma unroll
            for (int mt = 0; mt < 4; mt++) {
                int m0 = wm + mt * 16 + groupID;
                af[mt][0] = As[kb + m0];
                af[mt][1] = As[kb + m0 + 8];
                af[mt][2] = As[kb + 4 * KSTR + m0];
                af[mt][3] = As[kb + 4 * KSTR + m0 + 8];
            }
#pragma unroll
            for (int nt = 0; nt < 4; nt++) {
                int n0 = wn + nt * 8 + groupID;
                bf[nt][0] = Ws[kb + n0];
                bf[nt][1] = Ws[kb + 4 * KSTR + n0];
            }
#pragma unroll
            for (int mt = 0; mt < 4; mt++)
#pragma unroll
                for (int nt = 0; nt < 4; nt++)
                    mma_tf32(c[mt][nt][0], c[mt][nt][1], c[mt][nt][2], c[mt][nt][3],
                             af[mt][0], af[mt][1], af[mt][2], af[mt][3],
                             bf[nt][0], bf[nt][1]);
        }

        if (more) {
            __syncthreads();
            As[(lk + 0) * KSTR + lm] = f2tf32(ax.x);
            As[(lk + 1) * KSTR + lm] = f2tf32(ax.y);
            As[(lk + 2) * KSTR + lm] = f2tf32(ax.z);
            As[(lk + 3) * KSTR + lm] = f2tf32(ax.w);
            As[(lk + 4) * KSTR + lm] = f2tf32(ay.x);
            As[(lk + 5) * KSTR + lm] = f2tf32(ay.y);
            As[(lk + 6) * KSTR + lm] = f2tf32(ay.z);
            As[(lk + 7) * KSTR + lm] = f2tf32(ay.w);
            Ws[(lk + 0) * KSTR + lm] = f2tf32(wx.x);
            Ws[(lk + 1) * KSTR + lm] = f2tf32(wx.y);
            Ws[(lk + 2) * KSTR + lm] = f2tf32(wx.z);
            Ws[(lk + 3) * KSTR + lm] = f2tf32(wx.w);
            Ws[(lk + 4) * KSTR + lm] = f2tf32(wy.x);
            Ws[(lk + 5) * KSTR + lm] = f2tf32(wy.y);
            Ws[(lk + 6) * KSTR + lm] = f2tf32(wy.z);
            Ws[(lk + 7) * KSTR + lm] = f2tf32(wy.w);
            __syncthreads();
        }
    }

#pragma unroll
    for (int mt = 0; mt < 4; mt++) {
#pragma unroll
        for (int rr = 0; rr < 2; rr++) {
            int row = bm + wm + mt * 16 + groupID + rr * 8;
            float sc = (EPI == 1) ? g_invcnt[row >> 9] : 1.0f;
#pragma unroll
            for (int nt = 0; nt < 4; nt++) {
                int col = bn + wn + nt * 8 + tlane * 2;
                float v0 = c[mt][nt][rr * 2 + 0];
                float v1 = c[mt][nt][rr * 2 + 1];
                if (EPI == 1) {
                    v0 = (v0 + A[(size_t)row * D_ + col]) * sc;
                    v1 = (v1 + A[(size_t)row * D_ + col + 1]) * sc;
                }
                if (bias) {
                    v0 += bias[col];
                    v1 += bias[col + 1];
                }
                float2 r2;
                r2.x = v0; r2.y = v1;
                *(float2*)&C[(size_t)row * D_ + col] = r2;
            }
        }
    }
}

// ---------------- t = q + mq[seg] -------------------------------------------
__global__ void add_t_kernel(void) {
    int idx4 = blockIdx.x * blockDim.x + threadIdx.x;
    if (idx4 >= BND_ / 4) return;
    int idx = idx4 * 4;
    int b = idx / ND_;
    int off = idx - b * ND_;
    int sg = g_seg[b];
    float4 qv = *(const float4*)&g_q[idx];
    float4 mv = *(const float4*)&g_mq[(size_t)sg * ND_ + off];
    float4 r;
    r.x = qv.x + mv.x; r.y = qv.y + mv.y;
    r.z = qv.z + mv.z; r.w = qv.w + mv.w;
    *(float4*)&g_t[idx] = r;
}

// ---------------- tf32 MMA flash attention (BM=64, BN=64, 4 warps) ----------
// smem tiles (row-natural, stride 72 words => all fragment reads conflict-free):
//   Qs[64][72] tf32 (scaled by 1/8), Ks[64][72], Vs[64][72], Ps[64][72]
// Each warp owns 16 query rows -> softmax + P tile are warp-private.
#define ASTR 72
#define ATTN_SMEM (4 * 64 * ASTR * 4)
__global__ __launch_bounds__(128) void attn_mma_kernel(
    const float* __restrict__ Qg, const float* __restrict__ Kg,
    const float* __restrict__ Vg, float* __restrict__ Og)
{
    extern __shared__ uint32_t sm[];
    uint32_t* Qs = sm;
    uint32_t* Ks = sm + 64 * ASTR;
    uint32_t* Vs = sm + 2 * 64 * ASTR;
    uint32_t* Ps = sm + 3 * 64 * ASTR;

    const int b = blockIdx.z, h = blockIdx.y;
    const int n0 = blockIdx.x * 64;
    const size_t base = (size_t)b * ND_ + (size_t)h * HD_;
    const float* Qb = Qg + base + (size_t)n0 * D_;
    const float* Kb = Kg + base;
    const float* Vb = Vg + base;
    float*       Ob = Og + base + (size_t)n0 * D_;

    const int t = threadIdx.x;
    const int lane = t & 31;
    const int warp = t >> 5;
    const int g = lane >> 2;
    const int tl = lane & 3;
    const int wm = warp * 16;   // warp's 16 query rows

    // load Q tile (64x64) -> Qs[row][hd], tf32, scale 0.125 folded in
    {
        int row = t >> 1, c0 = (t & 1) * 32;
        const float* src = Qb + (size_t)row * D_ + c0;
        uint4* dst = (uint4*)&Qs[row * ASTR + c0];
#pragma unroll
        for (int i = 0; i < 8; i++) {
            float4 v = *(const float4*)(src + i * 4);
            uint4 u;
            u.x = f2tf32(v.x * 0.125f);
            u.y = f2tf32(v.y * 0.125f);
            u.z = f2tf32(v.z * 0.125f);
            u.w = f2tf32(v.w * 0.125f);
            dst[i] = u;
        }
    }

    float co[8][4];
#pragma unroll
    for (int nt = 0; nt < 8; nt++)
#pragma unroll
        for (int r = 0; r < 4; r++) co[nt][r] = 0.0f;
    float m0 = -INFINITY, m1 = -INFINITY, l0 = 0.0f, l1 = 0.0f;

    for (int kt = 0; kt < N_; kt += 64) {
        __syncthreads();   // prior Ks/Vs fully consumed; Qs visible on iter 0
        // load K,V tiles (64 keys x 64) -> Ks/Vs[key][hd], tf32
        {
            int row = t >> 1, c0 = (t & 1) * 32;
            const float* ksrc = Kb + (size_t)(kt + row) * D_ + c0;
            const float* vsrc = Vb + (size_t)(kt + row) * D_ + c0;
            uint4* kdst = (uint4*)&Ks[row * ASTR + c0];
            uint4* vdst = (uint4*)&Vs[row * ASTR + c0];
#pragma unroll
            for (int i = 0; i < 8; i++) {
                float4 kv = *(const float4*)(ksrc + i * 4);
                float4 vv = *(const float4*)(vsrc + i * 4);
                uint4 ku, vu;
                ku.x = f2tf32(kv.x); ku.y = f2tf32(kv.y);
                ku.z = f2tf32(kv.z); ku.w = f2tf32(kv.w);
                vu.x = f2tf32(vv.x); vu.y = f2tf32(vv.y);
                vu.z = f2tf32(vv.z); vu.w = f2tf32(vv.w);
                kdst[i] = ku;
                vdst[i] = vu;
            }
        }
        __syncthreads();

        // S = Q K^T for this warp's 16 rows x 64 keys
        float cs[8][4];
#pragma unroll
        for (int nt = 0; nt < 8; nt++)
#pragma unroll
            for (int r = 0; r < 4; r++) cs[nt][r] = 0.0f;
#pragma unroll
        for (int ks = 0; ks < 64; ks += 8) {
            uint32_t a0 = Qs[(wm + g) * ASTR + ks + tl];
            uint32_t a1 = Qs[(wm + g + 8) * ASTR + ks + tl];
            uint32_t a2 = Qs[(wm + g) * ASTR + ks + tl + 4];
            uint32_t a3 = Qs[(wm + g + 8) * ASTR + ks + tl + 4];
#pragma unroll
            for (int nt = 0; nt < 8; nt++) {
                uint32_t b0 = Ks[(nt * 8 + g) * ASTR + ks + tl];
                uint32_t b1 = Ks[(nt * 8 + g) * ASTR + ks + tl + 4];
                mma_tf32(cs[nt][0], cs[nt][1], cs[nt][2], cs[nt][3],
                         a0, a1, a2, a3, b0, b1);
            }
        }

        // online softmax (rows wm+g and wm+g+8; 64 cols spread over 4 tl lanes)
        float mt0 = -INFINITY, mt1 = -INFINITY;
#pragma unroll
        for (int nt = 0; nt < 8; nt++) {
            mt0 = fmaxf(mt0, fmaxf(cs[nt][0], cs[nt][1]));
            mt1 = fmaxf(mt1, fmaxf(cs[nt][2], cs[nt][3]));
        }
        mt0 = fmaxf(mt0, __shfl_xor_sync(0xffffffffu, mt0, 1));
        mt0 = fmaxf(mt0, __shfl_xor_sync(0xffffffffu, mt0, 2));
        mt1 = fmaxf(mt1, __shfl_xor_sync(0xffffffffu, mt1, 1));
        mt1 = fmaxf(mt1, __shfl_xor_sync(0xffffffffu, mt1, 2));

        float mn0 = fmaxf(m0, mt0), mn1 = fmaxf(m1, mt1);
        float corr0 = __expf(m0 - mn0), corr1 = __expf(m1 - mn1);
        m0 = mn0; m1 = mn1;

        float ls0 = 0.0f, ls1 = 0.0f;
#pragma unroll
        for (int nt = 0; nt < 8; nt++) {
            float p0 = __expf(cs[nt][0] - m0);
            float p1 = __expf(cs[nt][1] - m0);
            float p2 = __expf(cs[nt][2] - m1);
            float p3 = __expf(cs[nt][3] - m1);
            ls0 += p0 + p1;
            ls1 += p2 + p3;
            uint2 u01, u23;
            u01.x = f2tf32(p0); u01.y = f2tf32(p1);
            u23.x = f2tf32(p2); u23.y = f2tf32(p3);
            *(uint2*)&Ps[(wm + g) * ASTR + nt * 8 + 2 * tl] = u01;
            *(uint2*)&Ps[(wm + g + 8) * ASTR + nt * 8 + 2 * tl] = u23;
        }
        ls0 += __shfl_xor_sync(0xffffffffu, ls0, 1);
        ls0 += __shfl_xor_sync(0xffffffffu, ls0, 2);
        ls1 += __shfl_xor_sync(0xffffffffu, ls1, 1);
        ls1 += __shfl_xor_sync(0xffffffffu, ls1, 2);
        l0 = l0 * corr0 + ls0;
        l1 = l1 * corr1 + ls1;
#pragma unroll
        for (int nt = 0; nt < 8; nt++) {
            co[nt][0] *= corr0; co[nt][1] *= corr0;
            co[nt][2] *= corr1; co[nt][3] *= corr1;
        }
        __syncwarp();   // P tile (warp-private rows) visible to all lanes

        // O += P V
#pragma unroll
        for (int kk = 0; kk < 64; kk += 8) {
            uint32_t a0 = Ps[(wm + g) * ASTR + kk + tl];
            uint32_t a1 = Ps[(wm + g + 8) * ASTR + kk + tl];
            uint32_t a2 = Ps[(wm + g) * ASTR + kk + tl + 4];
            uint32_t a3 = Ps[(wm + g + 8) * ASTR + kk + tl + 4];
#pragma unroll
            for (int nt = 0; nt < 8; nt++) {
                uint32_t b0 = Vs[(kk + tl) * ASTR + nt * 8 + g];
                uint32_t b1 = Vs[(kk + tl + 4) * ASTR + nt * 8 + g];
                mma_tf32(co[nt][0], co[nt][1], co[nt][2], co[nt][3],
                         a0, a1, a2, a3, b0, b1);
            }
        }
    }

    // normalize + store
    float inv0 = 1.0f / l0, inv1 = 1.0f / l1;
#pragma unroll
    for (int nt = 0; nt < 8; nt++) {
        int col = nt * 8 + 2 * tl;
        float2 r0, r1;
        r0.x = co[nt][0] * inv0; r0.y = co[nt][1] * inv0;
        r1.x = co[nt][2] * inv1; r1.y = co[nt][3] * inv1;
        *(float2*)&Ob[(size_t)(wm + g) * D_ + col] = r0;
        *(float2*)&Ob[(size_t)(wm + g + 8) * D_ + col] = r1;
    }
}

// ---------------- host ------------------------------------------------------
extern "C" void kernel_launch(void* const* d_in, const int* in_sizes, int n_in,
                              void* d_out, int out_size)
{
    const float* hs  = (const float*)d_in[0];
    const void*  tid = d_in[1];
    const float* Wq = (const float*)d_in[2];
    const float* bq = (const float*)d_in[3];
    const float* Wk = (const float*)d_in[4];
    const float* bk = (const float*)d_in[5];
    const float* Wv = (const float*)d_in[6];
    const float* bv = (const float*)d_in[7];
    const float* Wo = (const float*)d_in[8];
    const float* bo = (const float*)d_in[9];
    const float* Wc = (const float*)d_in[10];
    const float* bc = (const float*)d_in[11];
    float* out = (float*)d_out;

    float *pS, *pMeans, *pMq, *pQ, *pK, *pV, *pT, *pVt, *pCtx;
    cudaGetSymbolAddress((void**)&pS, g_S);
    cudaGetSymbolAddress((void**)&pMeans, g_means);
    cudaGetSymbolAddress((void**)&pMq, g_mq);
    cudaGetSymbolAddress((void**)&pQ, g_q);
    cudaGetSymbolAddress((void**)&pK, g_k);
    cudaGetSymbolAddress((void**)&pV, g_v);
    cudaGetSymbolAddress((void**)&pT, g_t);
    cudaGetSymbolAddress((void**)&pVt, g_vt);
    cudaGetSymbolAddress((void**)&pCtx, g_ctx);

    cudaFuncSetAttribute(attn_mma_kernel,
                         cudaFuncAttributeMaxDynamicSharedMemorySize, ATTN_SMEM);

    // 1) segment ids + inverse counts
    seg_kernel<<<1, B_>>>(tid);
    // 2) per-group batch sums S[K,N,D]
    group_sum_kernel<<<ND_ / 256, 256>>>(hs);
    // 3) means = (S + S@Wc^T) * invcnt + bc   [K*N = 4096 rows]
    {
        dim3 g(D_ / 128, (K_ * N_) / 128);
        tf32_gemm_kernel<1><<<g, 256>>>(pS, Wc, bc, pMeans);
    }
    // 4) q,k,v projections of hs   [B*N = 16384 rows]
    {
        dim3 g(D_ / 128, (B_ * N_) / 128);
        tf32_gemm_kernel<0><<<g, 256>>>(hs, Wq, bq, pQ);
        tf32_gemm_kernel<0><<<g, 256>>>(hs, Wk, bk, pK);
        tf32_gemm_kernel<0><<<g, 256>>>(hs, Wv, bv, pV);
    }
    // 5) mq = means @ Wq^T (no bias; bias already in q)
    {
        dim3 g(D_ / 128, (K_ * N_) / 128);
        tf32_gemm_kernel<0><<<g, 256>>>(pMeans, Wq, nullptr, pMq);
    }
    // 6) t = q + mq[seg]
    add_t_kernel<<<(BND_ / 4) / 256, 256>>>();
    // 7) stage 1: v_t = softmax(t k^T / 8) v
    {
        dim3 g(N_ / 64, H_, B_);
        attn_mma_kernel<<<g, 128, ATTN_SMEM>>>(pT, pK, pV, pVt);
        // 8) stage 2: ctx = softmax(q t^T / 8) v_t
        attn_mma_kernel<<<g, 128, ATTN_SMEM>>>(pQ, pT, pVt, pCtx);
    }
    // 9) out = ctx @ Wo^T + bo
    {
        dim3 g(D_ / 128, (B_ * N_) / 128);
        tf32_gemm_kernel<0><<<g, 256>>>(pCtx, Wo, bo, out);
    }
}

// round 6
// speedup vs baseline: 2.9769x; 1.0648x over previous
#include <cuda_runtime.h>
#include <cuda_bf16.h>
#include <math.h>
#include <stdint.h>

// Problem constants
#define B_ 32
#define N_ 512
#define D_ 768
#define H_ 12
#define HD_ 64
#define K_ 8
#define BND_ (B_ * N_ * D_)   // 12,582,912
#define KND_ (K_ * N_ * D_)   // 3,145,728
#define ND_  (N_ * D_)        // 393,216

// ---------------- scratch (static device allocations; no cudaMalloc) -------
__device__ float g_S[KND_];
__device__ float g_means[KND_];
__device__ float g_mq[KND_];
__device__ float g_q[BND_];
__device__ float g_k[BND_];
__device__ float g_v[BND_];
__device__ float g_t[BND_];
__device__ float g_vt[BND_];
__device__ float g_ctx[BND_];
__device__ int   g_seg[B_];
__device__ float g_invcnt[K_];

// ---------------- seg + counts (handles int32 or int64 tid) ----------------
__global__ void seg_kernel(const void* __restrict__ tid_raw) {
    __shared__ int s[B_];
    int b = threadIdx.x;
    const int* p32 = (const int*)tid_raw;
    bool is64 = (p32[1] == 0);
    int v;
    if (is64) v = (int)((const long long*)tid_raw)[b];
    else      v = p32[b];
    s[b] = v - 1;
    g_seg[b] = v - 1;
    __syncthreads();
    if (b < K_) {
        int c = 0;
        for (int i = 0; i < B_; i++) c += (s[i] == b) ? 1 : 0;
        g_invcnt[b] = 1.0f / (float)(c > 0 ? c : 1);
    }
}

// ---------------- per-group batch sums: S[g,n,d] ----------------------------
__global__ void group_sum_kernel(const float* __restrict__ hs) {
    __shared__ int seg_s[B_];
    if (threadIdx.x < B_) seg_s[threadIdx.x] = g_seg[threadIdx.x];
    __syncthreads();
    int idx = blockIdx.x * blockDim.x + threadIdx.x;
    if (idx >= ND_) return;
    float acc[K_];
#pragma unroll
    for (int g = 0; g < K_; g++) acc[g] = 0.0f;
#pragma unroll
    for (int b = 0; b < B_; b++) {
        float val = hs[(size_t)b * ND_ + idx];
        int sg = seg_s[b];
#pragma unroll
        for (int g = 0; g < K_; g++) acc[g] += (sg == g) ? val : 0.0f;
    }
#pragma unroll
    for (int g = 0; g < K_; g++) g_S[(size_t)g * ND_ + idx] = acc[g];
}

// ---------------- tf32 helpers ----------------------------------------------
__device__ __forceinline__ uint32_t f2tf32(float x) {
    uint32_t r;
    asm("cvt.rna.tf32.f32 %0, %1;" : "=r"(r) : "f"(x));
    return r;
}

__device__ __forceinline__ void mma_tf32(
    float& c0, float& c1, float& c2, float& c3,
    uint32_t a0, uint32_t a1, uint32_t a2, uint32_t a3,
    uint32_t b0, uint32_t b1)
{
    asm volatile(
        "mma.sync.aligned.m16n8k8.row.col.f32.tf32.tf32.f32 "
        "{%0,%1,%2,%3},{%4,%5,%6,%7},{%8,%9},{%0,%1,%2,%3};"
        : "+f"(c0), "+f"(c1), "+f"(c2), "+f"(c3)
        : "r"(a0), "r"(a1), "r"(a2), "r"(a3), "r"(b0), "r"(b1));
}

// ---------------- TF32 GEMM: C[M,768] = A[M,768] @ W[768,768]^T (+epilogue) -
// Double-buffered smem (2 stages x BK=16): ONE __syncthreads per K-step.
// EPI 0: C = acc + bias (bias may be null)
// EPI 1: C = (acc + A[row,e]) * invcnt[row>>9] + bias[e]
#define KSTR 136
#define NKT  (D_ / 16)   // 48 K-steps
template <int EPI>
__global__ __launch_bounds__(256, 2) void tf32_gemm_kernel(
    const float* __restrict__ A, const float* __restrict__ W,
    const float* __restrict__ bias, float* __restrict__ C)
{
    __shared__ uint32_t As[2][16 * KSTR];
    __shared__ uint32_t Ws[2][16 * KSTR];

    const int bm = blockIdx.y * 128;
    const int bn = blockIdx.x * 128;
    const int t = threadIdx.x;
    const int lane = t & 31;
    const int warp = t >> 5;
    const int wm = (warp & 1) * 64;
    const int wn = (warp >> 1) * 32;
    const int groupID = lane >> 2;
    const int tlane = lane & 3;

    const int lm = t & 127;
    const int lk = (t >> 7) * 8;
    const float* Ap = A + (size_t)(bm + lm) * D_ + lk;
    const float* Wp = W + (size_t)(bn + lm) * D_ + lk;

    float c[4][4][4];
#pragma unroll
    for (int i = 0; i < 4; i++)
#pragma unroll
        for (int j = 0; j < 4; j++)
#pragma unroll
            for (int r = 0; r < 4; r++) c[i][j][r] = 0.0f;

    // prologue: stage 0 <- tile 0
    {
        float4 ax = *(const float4*)(Ap);
        float4 ay = *(const float4*)(Ap + 4);
        float4 wx = *(const float4*)(Wp);
        float4 wy = *(const float4*)(Wp + 4);
        uint32_t* as0 = As[0];
        uint32_t* ws0 = Ws[0];
        as0[(lk + 0) * KSTR + lm] = f2tf32(ax.x);
        as0[(lk + 1) * KSTR + lm] = f2tf32(ax.y);
        as0[(lk + 2) * KSTR + lm] = f2tf32(ax.z);
        as0[(lk + 3) * KSTR + lm] = f2tf32(ax.w);
        as0[(lk + 4) * KSTR + lm] = f2tf32(ay.x);
        as0[(lk + 5) * KSTR + lm] = f2tf32(ay.y);
        as0[(lk + 6) * KSTR + lm] = f2tf32(ay.z);
        as0[(lk + 7) * KSTR + lm] = f2tf32(ay.w);
        ws0[(lk + 0) * KSTR + lm] = f2tf32(wx.x);
        ws0[(lk + 1) * KSTR + lm] = f2tf32(wx.y);
        ws0[(lk + 2) * KSTR + lm] = f2tf32(wx.z);
        ws0[(lk + 3) * KSTR + lm] = f2tf32(wx.w);
        ws0[(lk + 4) * KSTR + lm] = f2tf32(wy.x);
        ws0[(lk + 5) * KSTR + lm] = f2tf32(wy.y);
        ws0[(lk + 6) * KSTR + lm] = f2tf32(wy.z);
        ws0[(lk + 7) * KSTR + lm] = f2tf32(wy.w);
    }
    __syncthreads();

#pragma unroll 1
    for (int it = 0; it < NKT; it++) {
        const int cur = it & 1;
        const bool more = (it + 1 < NKT);

        // prefetch next tile into registers (overlaps with MMAs below)
        float4 ax, ay, wx, wy;
        if (more) {
            int kt = (it + 1) * 16;
            ax = *(const float4*)(Ap + kt);
            ay = *(const float4*)(Ap + kt + 4);
            wx = *(const float4*)(Wp + kt);
            wy = *(const float4*)(Wp + kt + 4);
        }

        // compute current stage
        const uint32_t* asc = As[cur];
        const uint32_t* wsc = Ws[cur];
#pragma unroll
        for (int ks = 0; ks < 16; ks += 8) {
            uint32_t af[4][4];
            uint32_t bf[4][2];
            const int kb = (ks + tlane) * KSTR;
#pragma unroll
            for (int mt = 0; mt < 4; mt++) {
                int m0 = wm + mt * 16 + groupID;
                af[mt][0] = asc[kb + m0];
                af[mt][1] = asc[kb + m0 + 8];
                af[mt][2] = asc[kb + 4 * KSTR + m0];
                af[mt][3] = asc[kb + 4 * KSTR + m0 + 8];
            }
#pragma unroll
            for (int nt = 0; nt < 4; nt++) {
                int n0 = wn + nt * 8 + groupID;
                bf[nt][0] = wsc[kb + n0];
                bf[nt][1] = wsc[kb + 4 * KSTR + n0];
            }
#pragma unroll
            for (int mt = 0; mt < 4; mt++)
#pragma unroll
                for (int nt = 0; nt < 4; nt++)
                    mma_tf32(c[mt][nt][0], c[mt][nt][1], c[mt][nt][2], c[mt][nt][3],
                             af[mt][0], af[mt][1], af[mt][2], af[mt][3],
                             bf[nt][0], bf[nt][1]);
        }

        // store next tile into the other stage (no sync needed before: distinct buffer,
        // all warps finished reading it at the PREVIOUS iteration's barrier)
        if (more) {
            uint32_t* asn = As[cur ^ 1];
            uint32_t* wsn = Ws[cur ^ 1];
            asn[(lk + 0) * KSTR + lm] = f2tf32(ax.x);
            asn[(lk + 1) * KSTR + lm] = f2tf32(ax.y);
            asn[(lk + 2) * KSTR + lm] = f2tf32(ax.z);
            asn[(lk + 3) * KSTR + lm] = f2tf32(ax.w);
            asn[(lk + 4) * KSTR + lm] = f2tf32(ay.x);
            asn[(lk + 5) * KSTR + lm] = f2tf32(ay.y);
            asn[(lk + 6) * KSTR + lm] = f2tf32(ay.z);
            asn[(lk + 7) * KSTR + lm] = f2tf32(ay.w);
            wsn[(lk + 0) * KSTR + lm] = f2tf32(wx.x);
            wsn[(lk + 1) * KSTR + lm] = f2tf32(wx.y);
            wsn[(lk + 2) * KSTR + lm] = f2tf32(wx.z);
            wsn[(lk + 3) * KSTR + lm] = f2tf32(wx.w);
            wsn[(lk + 4) * KSTR + lm] = f2tf32(wy.x);
            wsn[(lk + 5) * KSTR + lm] = f2tf32(wy.y);
            wsn[(lk + 6) * KSTR + lm] = f2tf32(wy.z);
            wsn[(lk + 7) * KSTR + lm] = f2tf32(wy.w);
            __syncthreads();
        }
    }

    // epilogue
#pragma unroll
    for (int mt = 0; mt < 4; mt++) {
#pragma unroll
        for (int rr = 0; rr < 2; rr++) {
            int row = bm + wm + mt * 16 + groupID + rr * 8;
            float sc = (EPI == 1) ? g_invcnt[row >> 9] : 1.0f;
#pragma unroll
            for (int nt = 0; nt < 4; nt++) {
                int col = bn + wn + nt * 8 + tlane * 2;
                float v0 = c[mt][nt][rr * 2 + 0];
                float v1 = c[mt][nt][rr * 2 + 1];
                if (EPI == 1) {
                    v0 = (v0 + A[(size_t)row * D_ + col]) * sc;
                    v1 = (v1 + A[(size_t)row * D_ + col + 1]) * sc;
                }
                if (bias) {
                    v0 += bias[col];
                    v1 += bias[col + 1];
                }
                float2 r2;
                r2.x = v0; r2.y = v1;
                *(float2*)&C[(size_t)row * D_ + col] = r2;
            }
        }
    }
}

// ---------------- t = q + mq[seg] -------------------------------------------
__global__ void add_t_kernel(void) {
    int idx4 = blockIdx.x * blockDim.x + threadIdx.x;
    if (idx4 >= BND_ / 4) return;
    int idx = idx4 * 4;
    int b = idx / ND_;
    int off = idx - b * ND_;
    int sg = g_seg[b];
    float4 qv = *(const float4*)&g_q[idx];
    float4 mv = *(const float4*)&g_mq[(size_t)sg * ND_ + off];
    float4 r;
    r.x = qv.x + mv.x; r.y = qv.y + mv.y;
    r.z = qv.z + mv.z; r.w = qv.w + mv.w;
    *(float4*)&g_t[idx] = r;
}

// ---------------- tf32 MMA flash attention (BM=64, BN=64, 4 warps) ----------
#define ASTR 72
#define ATTN_SMEM (4 * 64 * ASTR * 4)
__global__ __launch_bounds__(128) void attn_mma_kernel(
    const float* __restrict__ Qg, const float* __restrict__ Kg,
    const float* __restrict__ Vg, float* __restrict__ Og)
{
    extern __shared__ uint32_t sm[];
    uint32_t* Qs = sm;
    uint32_t* Ks = sm + 64 * ASTR;
    uint32_t* Vs = sm + 2 * 64 * ASTR;
    uint32_t* Ps = sm + 3 * 64 * ASTR;

    const int b = blockIdx.z, h = blockIdx.y;
    const int n0 = blockIdx.x * 64;
    const size_t base = (size_t)b * ND_ + (size_t)h * HD_;
    const float* Qb = Qg + base + (size_t)n0 * D_;
    const float* Kb = Kg + base;
    const float* Vb = Vg + base;
    float*       Ob = Og + base + (size_t)n0 * D_;

    const int t = threadIdx.x;
    const int lane = t & 31;
    const int warp = t >> 5;
    const int g = lane >> 2;
    const int tl = lane & 3;
    const int wm = warp * 16;

    {
        int row = t >> 1, c0 = (t & 1) * 32;
        const float* src = Qb + (size_t)row * D_ + c0;
        uint4* dst = (uint4*)&Qs[row * ASTR + c0];
#pragma unroll
        for (int i = 0; i < 8; i++) {
            float4 v = *(const float4*)(src + i * 4);
            uint4 u;
            u.x = f2tf32(v.x * 0.125f);
            u.y = f2tf32(v.y * 0.125f);
            u.z = f2tf32(v.z * 0.125f);
            u.w = f2tf32(v.w * 0.125f);
            dst[i] = u;
        }
    }

    float co[8][4];
#pragma unroll
    for (int nt = 0; nt < 8; nt++)
#pragma unroll
        for (int r = 0; r < 4; r++) co[nt][r] = 0.0f;
    float m0 = -INFINITY, m1 = -INFINITY, l0 = 0.0f, l1 = 0.0f;

    for (int kt = 0; kt < N_; kt += 64) {
        __syncthreads();
        {
            int row = t >> 1, c0 = (t & 1) * 32;
            const float* ksrc = Kb + (size_t)(kt + row) * D_ + c0;
            const float* vsrc = Vb + (size_t)(kt + row) * D_ + c0;
            uint4* kdst = (uint4*)&Ks[row * ASTR + c0];
            uint4* vdst = (uint4*)&Vs[row * ASTR + c0];
#pragma unroll
            for (int i = 0; i < 8; i++) {
                float4 kv = *(const float4*)(ksrc + i * 4);
                float4 vv = *(const float4*)(vsrc + i * 4);
                uint4 ku, vu;
                ku.x = f2tf32(kv.x); ku.y = f2tf32(kv.y);
                ku.z = f2tf32(kv.z); ku.w = f2tf32(kv.w);
                vu.x = f2tf32(vv.x); vu.y = f2tf32(vv.y);
                vu.z = f2tf32(vv.z); vu.w = f2tf32(vv.w);
                kdst[i] = ku;
                vdst[i] = vu;
            }
        }
        __syncthreads();

        float cs[8][4];
#pragma unroll
        for (int nt = 0; nt < 8; nt++)
#pragma unroll
            for (int r = 0; r < 4; r++) cs[nt][r] = 0.0f;
#pragma unroll
        for (int ks = 0; ks < 64; ks += 8) {
            uint32_t a0 = Qs[(wm + g) * ASTR + ks + tl];
            uint32_t a1 = Qs[(wm + g + 8) * ASTR + ks + tl];
            uint32_t a2 = Qs[(wm + g) * ASTR + ks + tl + 4];
            uint32_t a3 = Qs[(wm + g + 8) * ASTR + ks + tl + 4];
#pragma unroll
            for (int nt = 0; nt < 8; nt++) {
                uint32_t b0 = Ks[(nt * 8 + g) * ASTR + ks + tl];
                uint32_t b1 = Ks[(nt * 8 + g) * ASTR + ks + tl + 4];
                mma_tf32(cs[nt][0], cs[nt][1], cs[nt][2], cs[nt][3],
                         a0, a1, a2, a3, b0, b1);
            }
        }

        float mt0 = -INFINITY, mt1 = -INFINITY;
#pragma unroll
        for (int nt = 0; nt < 8; nt++) {
            mt0 = fmaxf(mt0, fmaxf(cs[nt][0], cs[nt][1]));
            mt1 = fmaxf(mt1, fmaxf(cs[nt][2], cs[nt][3]));
        }
        mt0 = fmaxf(mt0, __shfl_xor_sync(0xffffffffu, mt0, 1));
        mt0 = fmaxf(mt0, __shfl_xor_sync(0xffffffffu, mt0, 2));
        mt1 = fmaxf(mt1, __shfl_xor_sync(0xffffffffu, mt1, 1));
        mt1 = fmaxf(mt1, __shfl_xor_sync(0xffffffffu, mt1, 2));

        float mn0 = fmaxf(m0, mt0), mn1 = fmaxf(m1, mt1);
        float corr0 = __expf(m0 - mn0), corr1 = __expf(m1 - mn1);
        m0 = mn0; m1 = mn1;

        float ls0 = 0.0f, ls1 = 0.0f;
#pragma unroll
        for (int nt = 0; nt < 8; nt++) {
            float p0 = __expf(cs[nt][0] - m0);
            float p1 = __expf(cs[nt][1] - m0);
            float p2 = __expf(cs[nt][2] - m1);
            float p3 = __expf(cs[nt][3] - m1);
            ls0 += p0 + p1;
            ls1 += p2 + p3;
            uint2 u01, u23;
            u01.x = f2tf32(p0); u01.y = f2tf32(p1);
            u23.x = f2tf32(p2); u23.y = f2tf32(p3);
            *(uint2*)&Ps[(wm + g) * ASTR + nt * 8 + 2 * tl] = u01;
            *(uint2*)&Ps[(wm + g + 8) * ASTR + nt * 8 + 2 * tl] = u23;
        }
        ls0 += __shfl_xor_sync(0xffffffffu, ls0, 1);
        ls0 += __shfl_xor_sync(0xffffffffu, ls0, 2);
        ls1 += __shfl_xor_sync(0xffffffffu, ls1, 1);
        ls1 += __shfl_xor_sync(0xffffffffu, ls1, 2);
        l0 = l0 * corr0 + ls0;
        l1 = l1 * corr1 + ls1;
#pragma unroll
        for (int nt = 0; nt < 8; nt++) {
            co[nt][0] *= corr0; co[nt][1] *= corr0;
            co[nt][2] *= corr1; co[nt][3] *= corr1;
        }
        __syncwarp();

#pragma unroll
        for (int kk = 0; kk < 64; kk += 8) {
            uint32_t a0 = Ps[(wm + g) * ASTR + kk + tl];
            uint32_t a1 = Ps[(wm + g + 8) * ASTR + kk + tl];
            uint32_t a2 = Ps[(wm + g) * ASTR + kk + tl + 4];
            uint32_t a3 = Ps[(wm + g + 8) * ASTR + kk + tl + 4];
#pragma unroll
            for (int nt = 0; nt < 8; nt++) {
                uint32_t b0 = Vs[(kk + tl) * ASTR + nt * 8 + g];
                uint32_t b1 = Vs[(kk + tl + 4) * ASTR + nt * 8 + g];
                mma_tf32(co[nt][0], co[nt][1], co[nt][2], co[nt][3],
                         a0, a1, a2, a3, b0, b1);
            }
        }
    }

    float inv0 = 1.0f / l0, inv1 = 1.0f / l1;
#pragma unroll
    for (int nt = 0; nt < 8; nt++) {
        int col = nt * 8 + 2 * tl;
        float2 r0, r1;
        r0.x = co[nt][0] * inv0; r0.y = co[nt][1] * inv0;
        r1.x = co[nt][2] * inv1; r1.y = co[nt][3] * inv1;
        *(float2*)&Ob[(size_t)(wm + g) * D_ + col] = r0;
        *(float2*)&Ob[(size_t)(wm + g + 8) * D_ + col] = r1;
    }
}

// ---------------- host ------------------------------------------------------
extern "C" void kernel_launch(void* const* d_in, const int* in_sizes, int n_in,
                              void* d_out, int out_size)
{
    const float* hs  = (const float*)d_in[0];
    const void*  tid = d_in[1];
    const float* Wq = (const float*)d_in[2];
    const float* bq = (const float*)d_in[3];
    const float* Wk = (const float*)d_in[4];
    const float* bk = (const float*)d_in[5];
    const float* Wv = (const float*)d_in[6];
    const float* bv = (const float*)d_in[7];
    const float* Wo = (const float*)d_in[8];
    const float* bo = (const float*)d_in[9];
    const float* Wc = (const float*)d_in[10];
    const float* bc = (const float*)d_in[11];
    float* out = (float*)d_out;

    float *pS, *pMeans, *pMq, *pQ, *pK, *pV, *pT, *pVt, *pCtx;
    cudaGetSymbolAddress((void**)&pS, g_S);
    cudaGetSymbolAddress((void**)&pMeans, g_means);
    cudaGetSymbolAddress((void**)&pMq, g_mq);
    cudaGetSymbolAddress((void**)&pQ, g_q);
    cudaGetSymbolAddress((void**)&pK, g_k);
    cudaGetSymbolAddress((void**)&pV, g_v);
    cudaGetSymbolAddress((void**)&pT, g_t);
    cudaGetSymbolAddress((void**)&pVt, g_vt);
    cudaGetSymbolAddress((void**)&pCtx, g_ctx);

    cudaFuncSetAttribute(attn_mma_kernel,
                         cudaFuncAttributeMaxDynamicSharedMemorySize, ATTN_SMEM);

    // 1) segment ids + inverse counts
    seg_kernel<<<1, B_>>>(tid);
    // 2) per-group batch sums S[K,N,D]
    group_sum_kernel<<<ND_ / 256, 256>>>(hs);
    // 3) means = (S + S@Wc^T) * invcnt + bc   [K*N = 4096 rows]
    {
        dim3 g(D_ / 128, (K_ * N_) / 128);
        tf32_gemm_kernel<1><<<g, 256>>>(pS, Wc, bc, pMeans);
    }
    // 4) q,k,v projections of hs   [B*N = 16384 rows]
    {
        dim3 g(D_ / 128, (B_ * N_) / 128);
        tf32_gemm_kernel<0><<<g, 256>>>(hs, Wq, bq, pQ);
        tf32_gemm_kernel<0><<<g, 256>>>(hs, Wk, bk, pK);
        tf32_gemm_kernel<0><<<g, 256>>>(hs, Wv, bv, pV);
    }
    // 5) mq = means @ Wq^T (no bias; bias already in q)
    {
        dim3 g(D_ / 128, (K_ * N_) / 128);
        tf32_gemm_kernel<0><<<g, 256>>>(pMeans, Wq, nullptr, pMq);
    }
    // 6) t = q + mq[seg]
    add_t_kernel<<<(BND_ / 4) / 256, 256>>>();
    // 7) stage 1: v_t = softmax(t k^T / 8) v
    {
        dim3 g(N_ / 64, H_, B_);
        attn_mma_kernel<<<g, 128, ATTN_SMEM>>>(pT, pK, pV, pVt);
        // 8) stage 2: ctx = softmax(q t^T / 8) v_t
        attn_mma_kernel<<<g, 128, ATTN_SMEM>>>(pQ, pT, pVt, pCtx);
    }
    // 9) out = ctx @ Wo^T + bo
    {
        dim3 g(D_ / 128, (B_ * N_) / 128);
        tf32_gemm_kernel<0><<<g, 256>>>(pCtx, Wo, bo, out);
    }
}

// round 7
// speedup vs baseline: 3.4518x; 1.1595x over previous
#include <cuda_runtime.h>
#include <cuda_bf16.h>
#include <math.h>
#include <stdint.h>

// Problem constants
#define B_ 32
#define N_ 512
#define D_ 768
#define H_ 12
#define HD_ 64
#define K_ 8
#define BND_ (B_ * N_ * D_)   // 12,582,912
#define KND_ (K_ * N_ * D_)   // 3,145,728
#define ND_  (N_ * D_)        // 393,216
#define WSZ_ (D_ * D_)        // 589,824

// ---------------- scratch (static device allocations; no cudaMalloc) -------
__device__ float g_S[KND_];
__device__ float g_means[KND_];
__device__ float g_mq[KND_];
__device__ float g_q[BND_];
__device__ float g_k[BND_];
__device__ float g_v[BND_];
__device__ float g_t[BND_];
__device__ float g_vt[BND_];
__device__ float g_ctx[BND_];
__device__ float g_hsr[BND_];       // tf32-rounded hs
__device__ float g_wr[5 * WSZ_];    // tf32-rounded Wq,Wk,Wv,Wo,Wc
__device__ int   g_seg[B_];
__device__ float g_invcnt[K_];

// ---------------- tf32 helpers ----------------------------------------------
__device__ __forceinline__ uint32_t f2tf32(float x) {
    uint32_t r;
    asm("cvt.rna.tf32.f32 %0, %1;" : "=r"(r) : "f"(x));
    return r;
}
__device__ __forceinline__ float roundtf(float x) {
    return __uint_as_float(f2tf32(x));
}

__device__ __forceinline__ void mma_tf32(
    float& c0, float& c1, float& c2, float& c3,
    uint32_t a0, uint32_t a1, uint32_t a2, uint32_t a3,
    uint32_t b0, uint32_t b1)
{
    asm volatile(
        "mma.sync.aligned.m16n8k8.row.col.f32.tf32.tf32.f32 "
        "{%0,%1,%2,%3},{%4,%5,%6,%7},{%8,%9},{%0,%1,%2,%3};"
        : "+f"(c0), "+f"(c1), "+f"(c2), "+f"(c3)
        : "r"(a0), "r"(a1), "r"(a2), "r"(a3), "r"(b0), "r"(b1));
}

__device__ __forceinline__ void cp_async16(uint32_t saddr, const void* gptr) {
    asm volatile("cp.async.ca.shared.global [%0], [%1], 16;"
                 :: "r"(saddr), "l"(gptr));
}

// ---------------- elementwise tf32 rounding ---------------------------------
__global__ void round_kernel(const float* __restrict__ in,
                             float* __restrict__ out, int n4) {
    int i = blockIdx.x * blockDim.x + threadIdx.x;
    if (i >= n4) return;
    float4 v = ((const float4*)in)[i];
    float4 r;
    r.x = roundtf(v.x); r.y = roundtf(v.y);
    r.z = roundtf(v.z); r.w = roundtf(v.w);
    ((float4*)out)[i] = r;
}

// ---------------- seg + counts (handles int32 or int64 tid) ----------------
__global__ void seg_kernel(const void* __restrict__ tid_raw) {
    __shared__ int s[B_];
    int b = threadIdx.x;
    const int* p32 = (const int*)tid_raw;
    bool is64 = (p32[1] == 0);
    int v;
    if (is64) v = (int)((const long long*)tid_raw)[b];
    else      v = p32[b];
    s[b] = v - 1;
    g_seg[b] = v - 1;
    __syncthreads();
    if (b < K_) {
        int c = 0;
        for (int i = 0; i < B_; i++) c += (s[i] == b) ? 1 : 0;
        g_invcnt[b] = 1.0f / (float)(c > 0 ? c : 1);
    }
}

// ---------------- per-group batch sums: S[g,n,d] (tf32-rounded out) ---------
__global__ void group_sum_kernel(const float* __restrict__ hs) {
    __shared__ int seg_s[B_];
    if (threadIdx.x < B_) seg_s[threadIdx.x] = g_seg[threadIdx.x];
    __syncthreads();
    int idx = blockIdx.x * blockDim.x + threadIdx.x;
    if (idx >= ND_) return;
    float acc[K_];
#pragma unroll
    for (int g = 0; g < K_; g++) acc[g] = 0.0f;
#pragma unroll
    for (int b = 0; b < B_; b++) {
        float val = hs[(size_t)b * ND_ + idx];
        int sg = seg_s[b];
#pragma unroll
        for (int g = 0; g < K_; g++) acc[g] += (sg == g) ? val : 0.0f;
    }
#pragma unroll
    for (int g = 0; g < K_; g++)
        g_S[(size_t)g * ND_ + idx] = roundtf(acc[g]);
}

// ---------------- TF32 GEMM via cp.async 4-stage pipeline -------------------
// C[M,768] = A[M,768] @ W[768,768]^T. Operands PRE-ROUNDED to tf32 in gmem.
// smem per stage: A 128x16 + W 128x16, row stride 20 words (conflict-free).
// EPI 0: C = acc + bias; EPI 1: C = (acc + A[row,e]) * invcnt[row>>9] + bias.
// ROUND 1: store tf32-rounded output (for tensors consumed as MMA operands).
#define GSTR 20
#define STG_WORDS (128 * GSTR)                    // 2560 words per operand
#define GEMM_SMEM (4 * 2 * STG_WORDS * 4)         // 81920 bytes
#define NKT (D_ / 16)                             // 48
template <int EPI, int ROUND>
__global__ __launch_bounds__(256, 2) void tf32_gemm_kernel(
    const float* __restrict__ A, const float* __restrict__ W,
    const float* __restrict__ bias, float* __restrict__ C)
{
    extern __shared__ uint32_t smg[];
    const int bm = blockIdx.y * 128;
    const int bn = blockIdx.x * 128;
    const int t = threadIdx.x;
    const int lane = t & 31, warp = t >> 5;
    const int wm = (warp & 1) * 64, wn = (warp >> 1) * 32;
    const int g = lane >> 2, tl = lane & 3;

    // copy mapping: thread -> (row cm, k-half ck), 2x16B per operand per stage
    const int cm = t >> 1;
    const int ck = (t & 1) * 8;
    const float* Ap = A + (size_t)(bm + cm) * D_ + ck;
    const float* Wp = W + (size_t)(bn + cm) * D_ + ck;
    const uint32_t sbase = (uint32_t)__cvta_generic_to_shared(smg)
                         + (cm * GSTR + ck) * 4;

    float c[4][4][4];
#pragma unroll
    for (int i = 0; i < 4; i++)
#pragma unroll
        for (int j = 0; j < 4; j++)
#pragma unroll
            for (int r = 0; r < 4; r++) c[i][j][r] = 0.0f;

    // prologue: stages 0..2
#pragma unroll
    for (int s = 0; s < 3; s++) {
        uint32_t as = sbase + s * (2 * STG_WORDS * 4);
        uint32_t ws = as + STG_WORDS * 4;
        int kt = s * 16;
        cp_async16(as,      Ap + kt);
        cp_async16(as + 16, Ap + kt + 4);
        cp_async16(ws,      Wp + kt);
        cp_async16(ws + 16, Wp + kt + 4);
        asm volatile("cp.async.commit_group;");
    }

#pragma unroll 1
    for (int it = 0; it < NKT; it++) {
        asm volatile("cp.async.wait_group 2;");
        __syncthreads();

        const uint32_t* As = smg + (it & 3) * 2 * STG_WORDS;
        const uint32_t* Ws = As + STG_WORDS;
#pragma unroll
        for (int ks = 0; ks < 16; ks += 8) {
            const int kb = ks + tl;
            uint32_t af[4][4];
            uint32_t bf[4][2];
#pragma unroll
            for (int mt = 0; mt < 4; mt++) {
                int m0 = (wm + mt * 16 + g) * GSTR;
                af[mt][0] = As[m0 + kb];
                af[mt][1] = As[m0 + 8 * GSTR + kb];
                af[mt][2] = As[m0 + kb + 4];
                af[mt][3] = As[m0 + 8 * GSTR + kb + 4];
            }
#pragma unroll
            for (int nt = 0; nt < 4; nt++) {
                int n0 = (wn + nt * 8 + g) * GSTR;
                bf[nt][0] = Ws[n0 + kb];
                bf[nt][1] = Ws[n0 + kb + 4];
            }
#pragma unroll
            for (int mt = 0; mt < 4; mt++)
#pragma unroll
                for (int nt = 0; nt < 4; nt++)
                    mma_tf32(c[mt][nt][0], c[mt][nt][1], c[mt][nt][2], c[mt][nt][3],
                             af[mt][0], af[mt][1], af[mt][2], af[mt][3],
                             bf[nt][0], bf[nt][1]);
        }

        int nxt = it + 3;
        if (nxt < NKT) {
            uint32_t as = sbase + (nxt & 3) * (2 * STG_WORDS * 4);
            uint32_t ws = as + STG_WORDS * 4;
            int kt = nxt * 16;
            cp_async16(as,      Ap + kt);
            cp_async16(as + 16, Ap + kt + 4);
            cp_async16(ws,      Wp + kt);
            cp_async16(ws + 16, Wp + kt + 4);
        }
        asm volatile("cp.async.commit_group;");
    }

    // epilogue
#pragma unroll
    for (int mt = 0; mt < 4; mt++) {
#pragma unroll
        for (int rr = 0; rr < 2; rr++) {
            int row = bm + wm + mt * 16 + g + rr * 8;
            float sc = (EPI == 1) ? g_invcnt[row >> 9] : 1.0f;
#pragma unroll
            for (int nt = 0; nt < 4; nt++) {
                int col = bn + wn + nt * 8 + tl * 2;
                float v0 = c[mt][nt][rr * 2 + 0];
                float v1 = c[mt][nt][rr * 2 + 1];
                if (EPI == 1) {
                    v0 = (v0 + A[(size_t)row * D_ + col]) * sc;
                    v1 = (v1 + A[(size_t)row * D_ + col + 1]) * sc;
                }
                if (bias) {
                    v0 += bias[col];
                    v1 += bias[col + 1];
                }
                if (ROUND) {
                    v0 = roundtf(v0);
                    v1 = roundtf(v1);
                }
                float2 r2;
                r2.x = v0; r2.y = v1;
                *(float2*)&C[(size_t)row * D_ + col] = r2;
            }
        }
    }
}

// ---------------- t = round(q + mq[seg]) ------------------------------------
__global__ void add_t_kernel(void) {
    int idx4 = blockIdx.x * blockDim.x + threadIdx.x;
    if (idx4 >= BND_ / 4) return;
    int idx = idx4 * 4;
    int b = idx / ND_;
    int off = idx - b * ND_;
    int sg = g_seg[b];
    float4 qv = *(const float4*)&g_q[idx];
    float4 mv = *(const float4*)&g_mq[(size_t)sg * ND_ + off];
    float4 r;
    r.x = roundtf(qv.x + mv.x); r.y = roundtf(qv.y + mv.y);
    r.z = roundtf(qv.z + mv.z); r.w = roundtf(qv.w + mv.w);
    *(float4*)&g_t[idx] = r;
}

// ---------------- tf32 MMA flash attention (BM=64, BN=64, 4 warps) ----------
// Operands pre-rounded in gmem -> raw copies into smem. Output tf32-rounded.
#define ASTR 72
#define ATTN_SMEM (4 * 64 * ASTR * 4)
__global__ __launch_bounds__(128) void attn_mma_kernel(
    const float* __restrict__ Qg, const float* __restrict__ Kg,
    const float* __restrict__ Vg, float* __restrict__ Og)
{
    extern __shared__ uint32_t sm[];
    uint32_t* Qs = sm;
    uint32_t* Ks = sm + 64 * ASTR;
    uint32_t* Vs = sm + 2 * 64 * ASTR;
    uint32_t* Ps = sm + 3 * 64 * ASTR;

    const int b = blockIdx.z, h = blockIdx.y;
    const int n0 = blockIdx.x * 64;
    const size_t base = (size_t)b * ND_ + (size_t)h * HD_;
    const float* Qb = Qg + base + (size_t)n0 * D_;
    const float* Kb = Kg + base;
    const float* Vb = Vg + base;
    float*       Ob = Og + base + (size_t)n0 * D_;

    const int t = threadIdx.x;
    const int lane = t & 31;
    const int warp = t >> 5;
    const int g = lane >> 2;
    const int tl = lane & 3;
    const int wm = warp * 16;

    // load Q tile; *0.125 (power of two: preserves tf32-representability)
    {
        int row = t >> 1, c0 = (t & 1) * 32;
        const float* src = Qb + (size_t)row * D_ + c0;
        uint4* dst = (uint4*)&Qs[row * ASTR + c0];
#pragma unroll
        for (int i = 0; i < 8; i++) {
            float4 v = *(const float4*)(src + i * 4);
            uint4 u;
            u.x = __float_as_uint(v.x * 0.125f);
            u.y = __float_as_uint(v.y * 0.125f);
            u.z = __float_as_uint(v.z * 0.125f);
            u.w = __float_as_uint(v.w * 0.125f);
            dst[i] = u;
        }
    }

    float co[8][4];
#pragma unroll
    for (int nt = 0; nt < 8; nt++)
#pragma unroll
        for (int r = 0; r < 4; r++) co[nt][r] = 0.0f;
    float m0 = -INFINITY, m1 = -INFINITY, l0 = 0.0f, l1 = 0.0f;

    for (int kt = 0; kt < N_; kt += 64) {
        __syncthreads();
        {
            int row = t >> 1, c0 = (t & 1) * 32;
            const uint4* ksrc = (const uint4*)(Kb + (size_t)(kt + row) * D_ + c0);
            const uint4* vsrc = (const uint4*)(Vb + (size_t)(kt + row) * D_ + c0);
            uint4* kdst = (uint4*)&Ks[row * ASTR + c0];
            uint4* vdst = (uint4*)&Vs[row * ASTR + c0];
#pragma unroll
            for (int i = 0; i < 8; i++) {
                kdst[i] = ksrc[i];
                vdst[i] = vsrc[i];
            }
        }
        __syncthreads();

        float cs[8][4];
#pragma unroll
        for (int nt = 0; nt < 8; nt++)
#pragma unroll
            for (int r = 0; r < 4; r++) cs[nt][r] = 0.0f;
#pragma unroll
        for (int ks = 0; ks < 64; ks += 8) {
            uint32_t a0 = Qs[(wm + g) * ASTR + ks + tl];
            uint32_t a1 = Qs[(wm + g + 8) * ASTR + ks + tl];
            uint32_t a2 = Qs[(wm + g) * ASTR + ks + tl + 4];
            uint32_t a3 = Qs[(wm + g + 8) * ASTR + ks + tl + 4];
#pragma unroll
            for (int nt = 0; nt < 8; nt++) {
                uint32_t b0 = Ks[(nt * 8 + g) * ASTR + ks + tl];
                uint32_t b1 = Ks[(nt * 8 + g) * ASTR + ks + tl + 4];
                mma_tf32(cs[nt][0], cs[nt][1], cs[nt][2], cs[nt][3],
                         a0, a1, a2, a3, b0, b1);
            }
        }

        float mt0 = -INFINITY, mt1 = -INFINITY;
#pragma unroll
        for (int nt = 0; nt < 8; nt++) {
            mt0 = fmaxf(mt0, fmaxf(cs[nt][0], cs[nt][1]));
            mt1 = fmaxf(mt1, fmaxf(cs[nt][2], cs[nt][3]));
        }
        mt0 = fmaxf(mt0, __shfl_xor_sync(0xffffffffu, mt0, 1));
        mt0 = fmaxf(mt0, __shfl_xor_sync(0xffffffffu, mt0, 2));
        mt1 = fmaxf(mt1, __shfl_xor_sync(0xffffffffu, mt1, 1));
        mt1 = fmaxf(mt1, __shfl_xor_sync(0xffffffffu, mt1, 2));

        float mn0 = fmaxf(m0, mt0), mn1 = fmaxf(m1, mt1);
        float corr0 = __expf(m0 - mn0), corr1 = __expf(m1 - mn1);
        m0 = mn0; m1 = mn1;

        float ls0 = 0.0f, ls1 = 0.0f;
#pragma unroll
        for (int nt = 0; nt < 8; nt++) {
            float p0 = __expf(cs[nt][0] - m0);
            float p1 = __expf(cs[nt][1] - m0);
            float p2 = __expf(cs[nt][2] - m1);
            float p3 = __expf(cs[nt][3] - m1);
            ls0 += p0 + p1;
            ls1 += p2 + p3;
            uint2 u01, u23;
            u01.x = f2tf32(p0); u01.y = f2tf32(p1);
            u23.x = f2tf32(p2); u23.y = f2tf32(p3);
            *(uint2*)&Ps[(wm + g) * ASTR + nt * 8 + 2 * tl] = u01;
            *(uint2*)&Ps[(wm + g + 8) * ASTR + nt * 8 + 2 * tl] = u23;
        }
        ls0 += __shfl_xor_sync(0xffffffffu, ls0, 1);
        ls0 += __shfl_xor_sync(0xffffffffu, ls0, 2);
        ls1 += __shfl_xor_sync(0xffffffffu, ls1, 1);
        ls1 += __shfl_xor_sync(0xffffffffu, ls1, 2);
        l0 = l0 * corr0 + ls0;
        l1 = l1 * corr1 + ls1;
#pragma unroll
        for (int nt = 0; nt < 8; nt++) {
            co[nt][0] *= corr0; co[nt][1] *= corr0;
            co[nt][2] *= corr1; co[nt][3] *= corr1;
        }
        __syncwarp();

#pragma unroll
        for (int kk = 0; kk < 64; kk += 8) {
            uint32_t a0 = Ps[(wm + g) * ASTR + kk + tl];
            uint32_t a1 = Ps[(wm + g + 8) * ASTR + kk + tl];
            uint32_t a2 = Ps[(wm + g) * ASTR + kk + tl + 4];
            uint32_t a3 = Ps[(wm + g + 8) * ASTR + kk + tl + 4];
#pragma unroll
            for (int nt = 0; nt < 8; nt++) {
                uint32_t b0 = Vs[(kk + tl) * ASTR + nt * 8 + g];
                uint32_t b1 = Vs[(kk + tl + 4) * ASTR + nt * 8 + g];
                mma_tf32(co[nt][0], co[nt][1], co[nt][2], co[nt][3],
                         a0, a1, a2, a3, b0, b1);
            }
        }
    }

    // normalize + tf32-round + store (consumed as MMA operand downstream)
    float inv0 = 1.0f / l0, inv1 = 1.0f / l1;
#pragma unroll
    for (int nt = 0; nt < 8; nt++) {
        int col = nt * 8 + 2 * tl;
        float2 r0, r1;
        r0.x = roundtf(co[nt][0] * inv0); r0.y = roundtf(co[nt][1] * inv0);
        r1.x = roundtf(co[nt][2] * inv1); r1.y = roundtf(co[nt][3] * inv1);
        *(float2*)&Ob[(size_t)(wm + g) * D_ + col] = r0;
        *(float2*)&Ob[(size_t)(wm + g + 8) * D_ + col] = r1;
    }
}

// ---------------- host ------------------------------------------------------
extern "C" void kernel_launch(void* const* d_in, const int* in_sizes, int n_in,
                              void* d_out, int out_size)
{
    const float* hs  = (const float*)d_in[0];
    const void*  tid = d_in[1];
    const float* Wq = (const float*)d_in[2];
    const float* bq = (const float*)d_in[3];
    const float* Wk = (const float*)d_in[4];
    const float* bk = (const float*)d_in[5];
    const float* Wv = (const float*)d_in[6];
    const float* bv = (const float*)d_in[7];
    const float* Wo = (const float*)d_in[8];
    const float* bo = (const float*)d_in[9];
    const float* Wc = (const float*)d_in[10];
    const float* bc = (const float*)d_in[11];
    float* out = (float*)d_out;

    float *pS, *pMeans, *pMq, *pQ, *pK, *pV, *pT, *pVt, *pCtx, *pHsr, *pWr;
    cudaGetSymbolAddress((void**)&pS, g_S);
    cudaGetSymbolAddress((void**)&pMeans, g_means);
    cudaGetSymbolAddress((void**)&pMq, g_mq);
    cudaGetSymbolAddress((void**)&pQ, g_q);
    cudaGetSymbolAddress((void**)&pK, g_k);
    cudaGetSymbolAddress((void**)&pV, g_v);
    cudaGetSymbolAddress((void**)&pT, g_t);
    cudaGetSymbolAddress((void**)&pVt, g_vt);
    cudaGetSymbolAddress((void**)&pCtx, g_ctx);
    cudaGetSymbolAddress((void**)&pHsr, g_hsr);
    cudaGetSymbolAddress((void**)&pWr, g_wr);
    float* pWq = pWr + 0 * WSZ_;
    float* pWk = pWr + 1 * WSZ_;
    float* pWv = pWr + 2 * WSZ_;
    float* pWo = pWr + 3 * WSZ_;
    float* pWc = pWr + 4 * WSZ_;

    cudaFuncSetAttribute(attn_mma_kernel,
                         cudaFuncAttributeMaxDynamicSharedMemorySize, ATTN_SMEM);
    cudaFuncSetAttribute(tf32_gemm_kernel<0, 0>,
                         cudaFuncAttributeMaxDynamicSharedMemorySize, GEMM_SMEM);
    cudaFuncSetAttribute(tf32_gemm_kernel<0, 1>,
                         cudaFuncAttributeMaxDynamicSharedMemorySize, GEMM_SMEM);
    cudaFuncSetAttribute(tf32_gemm_kernel<1, 1>,
                         cudaFuncAttributeMaxDynamicSharedMemorySize, GEMM_SMEM);

    // 0) pre-round operands to tf32 in gmem
    round_kernel<<<(BND_ / 4 + 255) / 256, 256>>>(hs, pHsr, BND_ / 4);
    round_kernel<<<(WSZ_ / 4 + 255) / 256, 256>>>(Wq, pWq, WSZ_ / 4);
    round_kernel<<<(WSZ_ / 4 + 255) / 256, 256>>>(Wk, pWk, WSZ_ / 4);
    round_kernel<<<(WSZ_ / 4 + 255) / 256, 256>>>(Wv, pWv, WSZ_ / 4);
    round_kernel<<<(WSZ_ / 4 + 255) / 256, 256>>>(Wo, pWo, WSZ_ / 4);
    round_kernel<<<(WSZ_ / 4 + 255) / 256, 256>>>(Wc, pWc, WSZ_ / 4);

    // 1) segment ids + inverse counts
    seg_kernel<<<1, B_>>>(tid);
    // 2) per-group batch sums S[K,N,D] (rounded)
    group_sum_kernel<<<ND_ / 256, 256>>>(hs);
    // 3) means = round((S + S@Wc^T) * invcnt + bc)
    {
        dim3 g(D_ / 128, (K_ * N_) / 128);
        tf32_gemm_kernel<1, 1><<<g, 256, GEMM_SMEM>>>(pS, pWc, bc, pMeans);
    }
    // 4) q,k,v projections (rounded outputs)
    {
        dim3 g(D_ / 128, (B_ * N_) / 128);
        tf32_gemm_kernel<0, 1><<<g, 256, GEMM_SMEM>>>(pHsr, pWq, bq, pQ);
        tf32_gemm_kernel<0, 1><<<g, 256, GEMM_SMEM>>>(pHsr, pWk, bk, pK);
        tf32_gemm_kernel<0, 1><<<g, 256, GEMM_SMEM>>>(pHsr, pWv, bv, pV);
    }
    // 5) mq = round(means @ Wq^T)
    {
        dim3 g(D_ / 128, (K_ * N_) / 128);
        tf32_gemm_kernel<0, 1><<<g, 256, GEMM_SMEM>>>(pMeans, pWq, nullptr, pMq);
    }
    // 6) t = round(q + mq[seg])
    add_t_kernel<<<(BND_ / 4) / 256, 256>>>();
    // 7) stage 1 + stage 2 attention
    {
        dim3 g(N_ / 64, H_, B_);
        attn_mma_kernel<<<g, 128, ATTN_SMEM>>>(pT, pK, pV, pVt);
        attn_mma_kernel<<<g, 128, ATTN_SMEM>>>(pQ, pT, pVt, pCtx);
    }
    // 9) out = ctx @ Wo^T + bo (full precision store)
    {
        dim3 g(D_ / 128, (B_ * N_) / 128);
        tf32_gemm_kernel<0, 0><<<g, 256, GEMM_SMEM>>>(pCtx, pWo, bo, out);
    }
}